// round 13
// baseline (speedup 1.0000x reference)
#include <cuda_runtime.h>
#include <math.h>
#include <stdint.h>

#define T_ 256
#define S_ 128
#define B_ 32
#define H_ 1024
#define NH_ 16
#define D_ 64
#define F_ 4096

// ---------------- scratch (static device globals; no allocation) ----------------
__device__ float g_q[(size_t)T_ * B_ * H_];
__device__ float g_k[(size_t)S_ * B_ * H_];
__device__ float g_v[(size_t)S_ * B_ * H_];
__device__ float g_ctx[(size_t)T_ * B_ * H_];
__device__ float g_attn[(size_t)T_ * B_ * H_];
__device__ float g_ffnh[(size_t)T_ * B_ * F_];
__device__ float g_ffnx[(size_t)T_ * B_ * H_];
__device__ float g_gpre[(size_t)T_ * B_ * 4 * H_];
__device__ float g_hbuf[2 * B_ * H_];
__device__ float g_cbuf[B_ * H_];
__device__ float g_xr[(size_t)T_ * B_ * H_];
__device__ float g_memr[(size_t)S_ * B_ * H_];
__device__ int   g_ctr[8 * T_];          // slot g at g*T_ + t  (1KB apart per slot)
// transposed tf32 weights
#define MM_ (1024 * 1024)
__device__ float g_wT[(size_t)24 * MM_];

// ---------------- PTX helpers ----------------------------------------------------
__device__ __forceinline__ uint32_t smem_to_u32(const void* p) {
    uint32_t a;
    asm("{ .reg .u64 t; cvta.to.shared.u64 t, %1; cvt.u32.u64 %0, t; }" : "=r"(a) : "l"(p));
    return a;
}
__device__ __forceinline__ uint32_t f2tf32(float x) {
    uint32_t u;
    asm("cvt.rna.tf32.f32 %0, %1;" : "=r"(u) : "f"(x));
    return u;
}
__device__ __forceinline__ void cp16(uint32_t s, const void* g) {
    asm volatile("cp.async.cg.shared.global [%0], [%1], 16;\n" :: "r"(s), "l"(g));
}
__device__ __forceinline__ void cp_commit() { asm volatile("cp.async.commit_group;\n"); }
template<int N> __device__ __forceinline__ void cp_wait() {
    asm volatile("cp.async.wait_group %0;\n" :: "n"(N));
}
__device__ __forceinline__ void ldsm4(uint32_t& r0, uint32_t& r1, uint32_t& r2,
                                      uint32_t& r3, uint32_t addr) {
    asm volatile("ldmatrix.sync.aligned.m8n8.x4.shared.b16 {%0,%1,%2,%3}, [%4];"
                 : "=r"(r0), "=r"(r1), "=r"(r2), "=r"(r3) : "r"(addr));
}
__device__ __forceinline__ void mma_tf32(float (&d)[4], const uint32_t (&a)[4],
                                         uint32_t b0, uint32_t b1) {
    asm volatile(
        "mma.sync.aligned.m16n8k8.row.col.f32.tf32.tf32.f32 "
        "{%0,%1,%2,%3}, {%4,%5,%6,%7}, {%8,%9}, {%0,%1,%2,%3};\n"
        : "+f"(d[0]), "+f"(d[1]), "+f"(d[2]), "+f"(d[3])
        : "r"(a[0]), "r"(a[1]), "r"(a[2]), "r"(a[3]), "r"(b0), "r"(b1));
}
__device__ __forceinline__ float sigmoidf_(float x) { return 1.f / (1.f + __expf(-x)); }

// ---------------- prepass kernels -------------------------------------------------
__global__ __launch_bounds__(256)
void transpose_tf32(const float* __restrict__ in, float* __restrict__ out, int R, int C)
{
    __shared__ float t[32][33];
    const int bx = blockIdx.x * 32;
    const int by = blockIdx.y * 32;
    const int tx = threadIdx.x & 31;
    const int ty = threadIdx.x >> 5;
#pragma unroll
    for (int i = 0; i < 4; i++)
        t[ty + 8 * i][tx] = in[(size_t)(by + ty + 8 * i) * C + bx + tx];
    __syncthreads();
#pragma unroll
    for (int i = 0; i < 4; i++)
        out[(size_t)(bx + ty + 8 * i) * R + by + tx] =
            __uint_as_float(f2tf32(t[tx][ty + 8 * i]));
}

__global__ __launch_bounds__(256)
void round_tf32(const float* __restrict__ in, float* __restrict__ out, int n)
{
    int i = blockIdx.x * 256 + threadIdx.x;
    for (; i < n; i += gridDim.x * 256)
        out[i] = __uint_as_float(f2tf32(in[i]));
}

__global__ void init_state(float* h, float* cc, int* ctr)
{
    int i = blockIdx.x * 256 + threadIdx.x;
    if (i < 2 * B_ * H_) h[i] = 0.f;
    if (i < B_ * H_) cc[i] = 0.f;
    if (i < 8 * T_) ctr[i] = 0;
}

// ---------------- tf32 mma GEMM: C[MxN] = A @ Bt^T ---------------------------------
// A: [M][K] fp32 (already tf32-rounded), dual-source rows [A(kSplit) | A2(K-kSplit)]
// Bt: [N][K] tf32. flags: 1=bias, 2=relu, 8=round output to tf32.
// 128x128x16 tile, 4-stage cp.async (DRAM-latency depth), ldmatrix fragments.
#define STG_ 20480   // A 128*80 + B 128*80
__global__ __launch_bounds__(256, 2)
void mm_gemm(const float* __restrict__ A, const float* __restrict__ A2, int kSplit,
             const float* __restrict__ Bt, const float* __restrict__ bias,
             float* __restrict__ C, int M, int N, int K, int flags)
{
    extern __shared__ char smc[];
    const uint32_t sb = smem_to_u32(smc);
    const int tid = threadIdx.x, lane = tid & 31, warp = tid >> 5;
    const int wm = warp >> 2, wn = warp & 3;
    const int m0 = blockIdx.y * 128, n0 = blockIdx.x * 128;
    const int lda2 = K - kSplit;
    const int nkt = K >> 4;

    auto fill = [&](int kt) {
        const int s = kt & 3;
        const uint32_t as = sb + s * STG_;
        const uint32_t bs = as + 10240;
        const int k0 = kt << 4;
#pragma unroll
        for (int i = 0; i < 2; i++) {
            int ch = tid + 256 * i;
            int row = ch >> 2, kh = ch & 3;
            int k = k0 + kh * 4;
            const float* src = (k < kSplit)
                ? A  + (size_t)(m0 + row) * kSplit + k
                : A2 + (size_t)(m0 + row) * lda2 + (k - kSplit);
            cp16(as + row * 80 + kh * 16, src);
        }
#pragma unroll
        for (int i = 0; i < 2; i++) {
            int ch = tid + 256 * i;
            int row = ch >> 2, kh = ch & 3;
            cp16(bs + row * 80 + kh * 16, Bt + (size_t)(n0 + row) * K + k0 + kh * 4);
        }
    };

    float acc[4][4][4];
#pragma unroll
    for (int i = 0; i < 4; i++)
#pragma unroll
        for (int j = 0; j < 4; j++)
#pragma unroll
            for (int r = 0; r < 4; r++) acc[i][j][r] = 0.f;

    fill(0); cp_commit();
    fill(1); cp_commit();
    fill(2); cp_commit();

    const uint32_t aoff = (uint32_t)((wm * 64 + (lane & 15)) * 80 + (lane >> 4) * 16);
    const uint32_t boff = (uint32_t)((wn * 32 + (lane & 15)) * 80 + (lane >> 4) * 16);

    for (int kt = 0; kt < nkt; kt++) {
        cp_wait<2>();
        __syncthreads();
        if (kt + 3 < nkt) fill(kt + 3);
        cp_commit();
        const uint32_t as = sb + (kt & 3) * STG_;
        const uint32_t bs = as + 10240;
#pragma unroll
        for (int ks = 0; ks < 2; ks++) {
            uint32_t af[4][4], bf[2][4];
#pragma unroll
            for (int mi = 0; mi < 4; mi++)
                ldsm4(af[mi][0], af[mi][1], af[mi][2], af[mi][3],
                      as + aoff + mi * (16 * 80) + ks * 32);
#pragma unroll
            for (int nip = 0; nip < 2; nip++)
                ldsm4(bf[nip][0], bf[nip][1], bf[nip][2], bf[nip][3],
                      bs + boff + nip * (16 * 80) + ks * 32);
#pragma unroll
            for (int mi = 0; mi < 4; mi++)
#pragma unroll
                for (int ni = 0; ni < 4; ni++) {
                    const int nip = ni >> 1, o = ni & 1;
                    mma_tf32(acc[mi][ni], af[mi], bf[nip][o], bf[nip][o + 2]);
                }
        }
    }

    const int g = lane >> 2, t = lane & 3;
#pragma unroll
    for (int mi = 0; mi < 4; mi++) {
#pragma unroll
        for (int ni = 0; ni < 4; ni++) {
            const int r0 = m0 + wm * 64 + mi * 16 + g;
            const int cc = n0 + wn * 32 + ni * 8 + 2 * t;
            float2 v0 = make_float2(acc[mi][ni][0], acc[mi][ni][1]);
            float2 v1 = make_float2(acc[mi][ni][2], acc[mi][ni][3]);
            if (flags & 1) {
                float2 bb = *(const float2*)(bias + cc);
                v0.x += bb.x; v0.y += bb.y; v1.x += bb.x; v1.y += bb.y;
            }
            if (flags & 2) {
                v0.x = fmaxf(v0.x, 0.f); v0.y = fmaxf(v0.y, 0.f);
                v1.x = fmaxf(v1.x, 0.f); v1.y = fmaxf(v1.y, 0.f);
            }
            if (flags & 8) {
                v0.x = __uint_as_float(f2tf32(v0.x)); v0.y = __uint_as_float(f2tf32(v0.y));
                v1.x = __uint_as_float(f2tf32(v1.x)); v1.y = __uint_as_float(f2tf32(v1.y));
            }
            *(float2*)(C + (size_t)r0 * N + cc) = v0;
            *(float2*)(C + (size_t)(r0 + 8) * N + cc) = v1;
        }
    }
}

// ---------------- attention ---------------------------------------------------------
#define ATT_PAD 68
#define ATT_SMEM_FLOATS ((64 + 128 + 128) * ATT_PAD + 8 * 128)

__global__ __launch_bounds__(256)
void attn_kernel(const float* __restrict__ q, const float* __restrict__ k,
                 const float* __restrict__ v, const float* __restrict__ sbias,
                 float* __restrict__ ctx)
{
    extern __shared__ float sm[];
    float* Qs = sm;
    float* Ks = sm + 64 * ATT_PAD;
    float* Vs = Ks + 128 * ATT_PAD;
    float* probs = Vs + 128 * ATT_PAD;

    const int b = blockIdx.x / NH_;
    const int h = blockIdx.x % NH_;
    const int t0 = blockIdx.y * 64;
    const int tid = threadIdx.x;
    const int lane = tid & 31;
    const int warp = tid >> 5;
    const int hd = h * D_;

    for (int e = tid; e < 128 * 16; e += 256) {
        int s = e >> 4;
        int d4 = (e & 15) << 2;
        size_t gofs = ((size_t)(s * B_ + b)) * H_ + hd + d4;
        *(float4*)&Ks[s * ATT_PAD + d4] = *(const float4*)&k[gofs];
        *(float4*)&Vs[s * ATT_PAD + d4] = *(const float4*)&v[gofs];
    }
    for (int e = tid; e < 64 * 16; e += 256) {
        int r = e >> 4;
        int d4 = (e & 15) << 2;
        *(float4*)&Qs[r * ATT_PAD + d4] =
            *(const float4*)&q[((size_t)((t0 + r) * B_ + b)) * H_ + hd + d4];
    }
    __syncthreads();

    const float scale = 0.125f;
    float* pw = probs + warp * 128;

    for (int r8 = 0; r8 < 8; r8++) {
        int row = warp * 8 + r8;
        const float4* qrow = (const float4*)&Qs[row * ATT_PAD];
        const float4* k0p = (const float4*)&Ks[(lane) * ATT_PAD];
        const float4* k1p = (const float4*)&Ks[(lane + 32) * ATT_PAD];
        const float4* k2p = (const float4*)&Ks[(lane + 64) * ATT_PAD];
        const float4* k3p = (const float4*)&Ks[(lane + 96) * ATT_PAD];
        float a0 = 0.f, a1 = 0.f, a2 = 0.f, a3 = 0.f;
#pragma unroll
        for (int d4 = 0; d4 < 16; d4++) {
            float4 qv = qrow[d4];
            float4 kv;
            kv = k0p[d4]; a0 += qv.x*kv.x + qv.y*kv.y + qv.z*kv.z + qv.w*kv.w;
            kv = k1p[d4]; a1 += qv.x*kv.x + qv.y*kv.y + qv.z*kv.z + qv.w*kv.w;
            kv = k2p[d4]; a2 += qv.x*kv.x + qv.y*kv.y + qv.z*kv.z + qv.w*kv.w;
            kv = k3p[d4]; a3 += qv.x*kv.x + qv.y*kv.y + qv.z*kv.z + qv.w*kv.w;
        }
        a0 = a0 * scale + sbias[b * S_ + lane];
        a1 = a1 * scale + sbias[b * S_ + lane + 32];
        a2 = a2 * scale + sbias[b * S_ + lane + 64];
        a3 = a3 * scale + sbias[b * S_ + lane + 96];

        float mx = fmaxf(fmaxf(a0, a1), fmaxf(a2, a3));
#pragma unroll
        for (int off = 16; off; off >>= 1)
            mx = fmaxf(mx, __shfl_xor_sync(0xffffffffu, mx, off));
        float e0 = __expf(a0 - mx), e1 = __expf(a1 - mx);
        float e2 = __expf(a2 - mx), e3 = __expf(a3 - mx);
        float ssum = e0 + e1 + e2 + e3;
#pragma unroll
        for (int off = 16; off; off >>= 1)
            ssum += __shfl_xor_sync(0xffffffffu, ssum, off);
        float inv = 1.f / ssum;

        pw[lane] = e0 * inv; pw[lane + 32] = e1 * inv;
        pw[lane + 64] = e2 * inv; pw[lane + 96] = e3 * inv;
        __syncwarp();

        float c0 = 0.f, c1 = 0.f;
#pragma unroll 4
        for (int s = 0; s < 128; s++) {
            float p = pw[s];
            c0 += p * Vs[s * ATT_PAD + lane];
            c1 += p * Vs[s * ATT_PAD + lane + 32];
        }
        float* crow = &ctx[((size_t)((t0 + row) * B_ + b)) * H_ + hd];
        crow[lane] = __uint_as_float(f2tf32(c0));
        crow[lane + 32] = __uint_as_float(f2tf32(c1));
        __syncwarp();
    }
}

// ---------------- persistent LSTM recurrence ---------------------------------------
// 128 CTAs, 1/SM. CTA n owns hidden cols [n*8, n*8+8) => 32 g-cols (4 gates x 8).
// Whh slice resident in smem. Per step: 8 tiles of 128 k-cols, 4-stage cp.async;
// warps (wm 2)x(wn 2)x(wk 2); fused gates (c in registers). Barrier: DISTRIBUTED
// arrivals across 8 slots (1KB apart -> distinct LTS slices; 16-way each) with
// parallel per-slot polling by threads 0..7 -> avoids 128-way single-address
// atomic serialization at the L2.
#define LP_BPITCH 4112
#define LP_APITCH 528
#define LP_ASTG   (32 * LP_APITCH)                  // 16896
#define LP_AOFF   131584                             // 32 * LP_BPITCH
#define LP_POFF   (LP_AOFF + 4 * LP_ASTG)            // 199168
#define LP_SMEM   (LP_POFF + 8 * 256 * 4)            // 207360

__global__ __launch_bounds__(256, 1)
void lstm_persist(const float* __restrict__ gpre, const float* __restrict__ WhhT,
                  float* __restrict__ hbuf, float* __restrict__ cbuf,
                  float* __restrict__ out, float* __restrict__ cf,
                  float* __restrict__ hf, int* __restrict__ ctr, int has_tail)
{
    extern __shared__ char smc[];
    const uint32_t sb = smem_to_u32(smc);
    const uint32_t Bs = sb;
    const uint32_t As = sb + LP_AOFF;
    float* part = (float*)(smc + LP_POFF);
    const int tid = threadIdx.x, lane = tid & 31, warp = tid >> 5;
    const int c0 = blockIdx.x * 8;
    const int slot = blockIdx.x & 7;

    // one-time: Whh slice -> smem. g-row (gate*8+j) maps WhhT row gate*1024+c0+j.
#pragma unroll 4
    for (int i = 0; i < 32; i++) {
        int id = tid + 256 * i;
        int row = id >> 8, ch = id & 255;
        int gate = row >> 3, j = row & 7;
        cp16(Bs + row * LP_BPITCH + ch * 16,
             WhhT + (size_t)(gate * H_ + c0 + j) * H_ + ch * 4);
    }
    cp_commit(); cp_wait<0>(); __syncthreads();

    const int wm = warp & 1, wn = (warp >> 1) & 1, wk = warp >> 2;
    const uint32_t aoff = (uint32_t)((wm * 16 + (lane & 15)) * LP_APITCH + (lane >> 4) * 16);
    const uint32_t boff = (uint32_t)((wn * 16 + (lane & 15)) * LP_BPITCH + (lane >> 4) * 16);
    const int row_e = tid >> 3, j_e = tid & 7;        // epilogue: batch row, hidden col
    const int idx_h = row_e * H_ + c0 + j_e;
    const int arow = tid >> 5, ach = tid & 31;        // A fill mapping

    float creg = 0.f;                                  // carry state in register
    float gpv[4];
#pragma unroll
    for (int gi = 0; gi < 4; gi++)
        gpv[gi] = __ldg(gpre + (size_t)row_e * (4 * H_) + gi * H_ + c0 + j_e);

    for (int t = 0; t < T_; t++) {
        const float* hin = hbuf + (t & 1) * (B_ * H_);
        float* hout = hbuf + (1 - (t & 1)) * (B_ * H_);

#define LP_FILL(kt_) do { \
            const uint32_t as_f = As + ((kt_) & 3) * LP_ASTG; \
            const float* hsrc = hin + arow * H_ + (kt_) * 128 + ach * 4; \
            _Pragma("unroll") \
            for (int i_ = 0; i_ < 4; i_++) \
                cp16(as_f + (arow + 8 * i_) * LP_APITCH + ach * 16, hsrc + 8 * i_ * H_); \
        } while (0)

        // deferred barrier wait: threads 0..7 each poll one slot in parallel
        if (t > 0) {
            if (tid < 8) {
                volatile int* vc = (volatile int*)&ctr[tid * T_ + (t - 1)];
                while (*vc < 16) __nanosleep(16);
            }
            __syncthreads();
        }
        LP_FILL(0); cp_commit();
        LP_FILL(1); cp_commit();
        LP_FILL(2); cp_commit();

        float acc[2][4];
#pragma unroll
        for (int i = 0; i < 2; i++)
#pragma unroll
            for (int r = 0; r < 4; r++) acc[i][r] = 0.f;

        for (int kt = 0; kt < 8; kt++) {
            cp_wait<2>();
            __syncthreads();
            if (kt + 3 < 8) LP_FILL(kt + 3);
            cp_commit();
            const uint32_t as_ = As + (kt & 3) * LP_ASTG;
            const uint32_t bk = Bs + boff + (uint32_t)kt * 512;
#pragma unroll
            for (int s8 = 0; s8 < 8; s8++) {
                const int s = wk * 8 + s8;
                uint32_t af[4], b0, b1, b2, b3;
                ldsm4(af[0], af[1], af[2], af[3], as_ + aoff + s * 32);
                ldsm4(b0, b1, b2, b3, bk + s * 32);
                mma_tf32(acc[0], af, b0, b2);
                mma_tf32(acc[1], af, b1, b3);
            }
        }

        // prefetch next step's gate bias early (overlaps epilogue + barrier)
        float gpn[4] = {0.f, 0.f, 0.f, 0.f};
        if (t + 1 < T_) {
            const float* gp1 = gpre + (size_t)(t + 1) * B_ * 4 * H_;
#pragma unroll
            for (int gi = 0; gi < 4; gi++)
                gpn[gi] = __ldg(gp1 + (size_t)row_e * (4 * H_) + gi * H_ + c0 + j_e);
        }

        // store per-warp partials [16x16]
        {
            const int g = lane >> 2, tq = lane & 3;
            float* pw = part + warp * 256;
#pragma unroll
            for (int ni = 0; ni < 2; ni++) {
                *(float2*)&pw[g * 16 + ni * 8 + 2 * tq] = make_float2(acc[ni][0], acc[ni][1]);
                *(float2*)&pw[(g + 8) * 16 + ni * 8 + 2 * tq] = make_float2(acc[ni][2], acc[ni][3]);
            }
        }
        __syncthreads();

        // combine k-halves + gpre; gates; state update
        {
            float gv[4];
#pragma unroll
            for (int gate = 0; gate < 4; gate++) {
                int ncol = gate * 8 + j_e;
                int w0 = (row_e >> 4) | ((ncol >> 4) << 1);
                int idx = (row_e & 15) * 16 + (ncol & 15);
                gv[gate] = part[w0 * 256 + idx] + part[(w0 + 4) * 256 + idx] + gpv[gate];
            }
            float iv = sigmoidf_(gv[0]);
            float jv = tanhf(gv[1]);
            float fv = sigmoidf_(gv[2]);
            float ov = sigmoidf_(gv[3]);
            float nc = fv * creg + iv * jv;
            float nh = ov * nc;                       // THUMT LSTMCell: activation=None
            creg = nc;
            __stwt(&out[(size_t)t * B_ * H_ + idx_h], nh);
            __stcg(&hout[idx_h], __uint_as_float(f2tf32(nh)));
            if (has_tail && t == T_ - 1) { cf[idx_h] = nc; hf[idx_h] = nh; }
        }
#pragma unroll
        for (int gi = 0; gi < 4; gi++) gpv[gi] = gpn[gi];

        // distributed barrier arrival (wait deferred to top of next step)
        __threadfence();
        __syncthreads();
        if (tid == 0) atomicAdd(&ctr[slot * T_ + t], 1);
    }
}

// ---------------- launch ------------------------------------------------------------
extern "C" void kernel_launch(void* const* d_in, const int* in_sizes, int n_in,
                              void* d_out, int out_size)
{
    (void)in_sizes; (void)n_in;
    const float* x  = (const float*)d_in[0];
    const float* sb = (const float*)d_in[1];
    const float* mem = (const float*)d_in[3];
    const float* Wq = (const float*)d_in[4];  const float* bq = (const float*)d_in[5];
    const float* Wk = (const float*)d_in[6];  const float* bk = (const float*)d_in[7];
    const float* Wv = (const float*)d_in[8];  const float* bv = (const float*)d_in[9];
    const float* Wo = (const float*)d_in[10]; const float* bo = (const float*)d_in[11];
    const float* W1 = (const float*)d_in[12]; const float* b1 = (const float*)d_in[13];
    const float* W2 = (const float*)d_in[14]; const float* b2 = (const float*)d_in[15];
    const float* Wg = (const float*)d_in[16]; const float* bg = (const float*)d_in[17];
    float* out = (float*)d_out;

    float *q, *k, *v, *ctx, *attn, *ffnh, *ffnx, *gpre, *hbuf, *cbuf, *wT, *xr, *memr;
    int* ctr;
    cudaGetSymbolAddress((void**)&q,    g_q);
    cudaGetSymbolAddress((void**)&k,    g_k);
    cudaGetSymbolAddress((void**)&v,    g_v);
    cudaGetSymbolAddress((void**)&ctx,  g_ctx);
    cudaGetSymbolAddress((void**)&attn, g_attn);
    cudaGetSymbolAddress((void**)&ffnh, g_ffnh);
    cudaGetSymbolAddress((void**)&ffnx, g_ffnx);
    cudaGetSymbolAddress((void**)&gpre, g_gpre);
    cudaGetSymbolAddress((void**)&hbuf, g_hbuf);
    cudaGetSymbolAddress((void**)&cbuf, g_cbuf);
    cudaGetSymbolAddress((void**)&wT,   g_wT);
    cudaGetSymbolAddress((void**)&xr,   g_xr);
    cudaGetSymbolAddress((void**)&memr, g_memr);
    cudaGetSymbolAddress((void**)&ctr,  g_ctr);

    float* WqT = wT;
    float* WkT = wT + (size_t)1 * MM_;
    float* WvT = wT + (size_t)2 * MM_;
    float* WoT = wT + (size_t)3 * MM_;
    float* W1T = wT + (size_t)4 * MM_;
    float* W2T = wT + (size_t)8 * MM_;
    float* WgT = wT + (size_t)12 * MM_;
    float* WhhT = wT + (size_t)20 * MM_;

    dim3 blk(256);

    // prepass: weight transpose + tf32 round; activation rounding
    transpose_tf32<<<dim3(H_ / 32, H_ / 32), blk>>>(Wq, WqT, H_, H_);
    transpose_tf32<<<dim3(H_ / 32, H_ / 32), blk>>>(Wk, WkT, H_, H_);
    transpose_tf32<<<dim3(H_ / 32, H_ / 32), blk>>>(Wv, WvT, H_, H_);
    transpose_tf32<<<dim3(H_ / 32, H_ / 32), blk>>>(Wo, WoT, H_, H_);
    transpose_tf32<<<dim3(F_ / 32, H_ / 32), blk>>>(W1, W1T, H_, F_);
    transpose_tf32<<<dim3(H_ / 32, F_ / 32), blk>>>(W2, W2T, F_, H_);
    transpose_tf32<<<dim3(F_ / 32, (2 * H_) / 32), blk>>>(Wg, WgT, 2 * H_, F_);
    transpose_tf32<<<dim3(F_ / 32, H_ / 32), blk>>>(
        Wg + (size_t)2 * H_ * 4 * H_, WhhT, H_, F_);
    round_tf32<<<1024, blk>>>(x, xr, T_ * B_ * H_);
    round_tf32<<<1024, blk>>>(mem, memr, S_ * B_ * H_);

    const int GSM = 4 * STG_;   // 81920
    cudaFuncSetAttribute(mm_gemm, cudaFuncAttributeMaxDynamicSharedMemorySize, GSM);
    cudaFuncSetAttribute(lstm_persist, cudaFuncAttributeMaxDynamicSharedMemorySize, LP_SMEM);

    // projections
    mm_gemm<<<dim3(H_ / 128, (T_ * B_) / 128), blk, GSM>>>(
        xr, xr, H_, WqT, bq, q, T_ * B_, H_, H_, 1);
    mm_gemm<<<dim3(H_ / 128, (S_ * B_) / 128), blk, GSM>>>(
        memr, memr, H_, WkT, bk, k, S_ * B_, H_, H_, 1);
    mm_gemm<<<dim3(H_ / 128, (S_ * B_) / 128), blk, GSM>>>(
        memr, memr, H_, WvT, bv, v, S_ * B_, H_, H_, 1);

    // attention
    size_t attn_smem = (size_t)ATT_SMEM_FLOATS * sizeof(float);
    cudaFuncSetAttribute(attn_kernel, cudaFuncAttributeMaxDynamicSharedMemorySize,
                         (int)attn_smem);
    attn_kernel<<<dim3(B_ * NH_, T_ / 64), blk, attn_smem>>>(q, k, v, sb, ctx);

    // output projection
    mm_gemm<<<dim3(H_ / 128, (T_ * B_) / 128), blk, GSM>>>(
        ctx, ctx, H_, WoT, bo, attn, T_ * B_, H_, H_, 1 | 8);

    // feed-forward
    mm_gemm<<<dim3(F_ / 128, (T_ * B_) / 128), blk, GSM>>>(
        xr, xr, H_, W1T, b1, ffnh, T_ * B_, F_, H_, 1 | 2 | 8);
    mm_gemm<<<dim3(H_ / 128, (T_ * B_) / 128), blk, GSM>>>(
        ffnh, ffnh, F_, W2T, b2, ffnx, T_ * B_, H_, F_, 1 | 8);

    // gate precompute (fused dual-source K=2048): gpre = [ffnx|attn] @ WgT^T + bg
    mm_gemm<<<dim3((4 * H_) / 128, (T_ * B_) / 128), blk, GSM>>>(
        ffnx, attn, H_, WgT, bg, gpre, T_ * B_, 4 * H_, 2 * H_, 1);

    // recurrence: one persistent launch, distributed-arrival barrier
    init_state<<<(2 * B_ * H_ + 255) / 256, 256>>>(hbuf, cbuf, ctr);
    int has_tail = out_size >= T_ * B_ * H_ + 2 * B_ * H_;
    float* cf = out + (size_t)T_ * B_ * H_;
    float* hf = cf + B_ * H_;
    lstm_persist<<<128, blk, LP_SMEM>>>(gpre, WhhT, hbuf, cbuf, out, cf, hf, ctr, has_tail);
}

// round 14
// speedup vs baseline: 1.1164x; 1.1164x over previous
#include <cuda_runtime.h>
#include <cuda_fp16.h>
#include <math.h>
#include <stdint.h>

#define T_ 256
#define S_ 128
#define B_ 32
#define H_ 1024
#define NH_ 16
#define D_ 64
#define F_ 4096

// ---------------- scratch (static device globals; no allocation) ----------------
__device__ float g_q[(size_t)T_ * B_ * H_];
__device__ float g_k[(size_t)S_ * B_ * H_];
__device__ float g_v[(size_t)S_ * B_ * H_];
__device__ float g_ctx[(size_t)T_ * B_ * H_];
__device__ float g_attn[(size_t)T_ * B_ * H_];
__device__ float g_ffnh[(size_t)T_ * B_ * F_];
__device__ float g_ffnx[(size_t)T_ * B_ * H_];
__device__ float g_gpre[(size_t)T_ * B_ * 4 * H_];
__device__ float g_hbuf[2 * B_ * H_];    // reinterpreted as __half[2][B*H] for recurrence
__device__ float g_cbuf[B_ * H_];
__device__ float g_xr[(size_t)T_ * B_ * H_];
__device__ float g_memr[(size_t)S_ * B_ * H_];
__device__ int   g_ctr[T_];
// transposed tf32 weights (+ fp16 Whh at +20MM)
#define MM_ (1024 * 1024)
__device__ float g_wT[(size_t)24 * MM_];

// ---------------- PTX helpers ----------------------------------------------------
__device__ __forceinline__ uint32_t smem_to_u32(const void* p) {
    uint32_t a;
    asm("{ .reg .u64 t; cvta.to.shared.u64 t, %1; cvt.u32.u64 %0, t; }" : "=r"(a) : "l"(p));
    return a;
}
__device__ __forceinline__ uint32_t f2tf32(float x) {
    uint32_t u;
    asm("cvt.rna.tf32.f32 %0, %1;" : "=r"(u) : "f"(x));
    return u;
}
__device__ __forceinline__ void cp16(uint32_t s, const void* g) {
    asm volatile("cp.async.cg.shared.global [%0], [%1], 16;\n" :: "r"(s), "l"(g));
}
__device__ __forceinline__ void cp_commit() { asm volatile("cp.async.commit_group;\n"); }
template<int N> __device__ __forceinline__ void cp_wait() {
    asm volatile("cp.async.wait_group %0;\n" :: "n"(N));
}
__device__ __forceinline__ void ldsm4(uint32_t& r0, uint32_t& r1, uint32_t& r2,
                                      uint32_t& r3, uint32_t addr) {
    asm volatile("ldmatrix.sync.aligned.m8n8.x4.shared.b16 {%0,%1,%2,%3}, [%4];"
                 : "=r"(r0), "=r"(r1), "=r"(r2), "=r"(r3) : "r"(addr));
}
__device__ __forceinline__ void mma_tf32(float (&d)[4], const uint32_t (&a)[4],
                                         uint32_t b0, uint32_t b1) {
    asm volatile(
        "mma.sync.aligned.m16n8k8.row.col.f32.tf32.tf32.f32 "
        "{%0,%1,%2,%3}, {%4,%5,%6,%7}, {%8,%9}, {%0,%1,%2,%3};\n"
        : "+f"(d[0]), "+f"(d[1]), "+f"(d[2]), "+f"(d[3])
        : "r"(a[0]), "r"(a[1]), "r"(a[2]), "r"(a[3]), "r"(b0), "r"(b1));
}
__device__ __forceinline__ void mma_f16(float (&d)[4], const uint32_t (&a)[4],
                                        uint32_t b0, uint32_t b1) {
    asm volatile(
        "mma.sync.aligned.m16n8k16.row.col.f32.f16.f16.f32 "
        "{%0,%1,%2,%3}, {%4,%5,%6,%7}, {%8,%9}, {%0,%1,%2,%3};\n"
        : "+f"(d[0]), "+f"(d[1]), "+f"(d[2]), "+f"(d[3])
        : "r"(a[0]), "r"(a[1]), "r"(a[2]), "r"(a[3]), "r"(b0), "r"(b1));
}
__device__ __forceinline__ float sigmoidf_(float x) { return 1.f / (1.f + __expf(-x)); }

// ---------------- prepass kernels -------------------------------------------------
__global__ __launch_bounds__(256)
void transpose_tf32(const float* __restrict__ in, float* __restrict__ out, int R, int C)
{
    __shared__ float t[32][33];
    const int bx = blockIdx.x * 32;
    const int by = blockIdx.y * 32;
    const int tx = threadIdx.x & 31;
    const int ty = threadIdx.x >> 5;
#pragma unroll
    for (int i = 0; i < 4; i++)
        t[ty + 8 * i][tx] = in[(size_t)(by + ty + 8 * i) * C + bx + tx];
    __syncthreads();
#pragma unroll
    for (int i = 0; i < 4; i++)
        out[(size_t)(bx + ty + 8 * i) * R + by + tx] =
            __uint_as_float(f2tf32(t[tx][ty + 8 * i]));
}

__global__ __launch_bounds__(256)
void transpose_f16(const float* __restrict__ in, __half* __restrict__ out, int R, int C)
{
    __shared__ float t[32][33];
    const int bx = blockIdx.x * 32;
    const int by = blockIdx.y * 32;
    const int tx = threadIdx.x & 31;
    const int ty = threadIdx.x >> 5;
#pragma unroll
    for (int i = 0; i < 4; i++)
        t[ty + 8 * i][tx] = in[(size_t)(by + ty + 8 * i) * C + bx + tx];
    __syncthreads();
#pragma unroll
    for (int i = 0; i < 4; i++)
        out[(size_t)(bx + ty + 8 * i) * R + by + tx] = __float2half(t[tx][ty + 8 * i]);
}

__global__ __launch_bounds__(256)
void round_tf32(const float* __restrict__ in, float* __restrict__ out, int n)
{
    int i = blockIdx.x * 256 + threadIdx.x;
    for (; i < n; i += gridDim.x * 256)
        out[i] = __uint_as_float(f2tf32(in[i]));
}

__global__ void init_state(float* h, float* cc, int* ctr)
{
    int i = blockIdx.x * 256 + threadIdx.x;
    if (i < 2 * B_ * H_) h[i] = 0.f;
    if (i < B_ * H_) cc[i] = 0.f;
    if (i < T_) ctr[i] = 0;
}

// ---------------- tf32 mma GEMM: C[MxN] = A @ Bt^T ---------------------------------
// A: [M][K] fp32 (already tf32-rounded), dual-source rows [A(kSplit) | A2(K-kSplit)]
// Bt: [N][K] tf32. flags: 1=bias, 2=relu, 8=round output to tf32.
// 128x128x16 tile, 4-stage cp.async, ldmatrix fragments.
#define STG_ 20480   // A 128*80 + B 128*80
__global__ __launch_bounds__(256, 2)
void mm_gemm(const float* __restrict__ A, const float* __restrict__ A2, int kSplit,
             const float* __restrict__ Bt, const float* __restrict__ bias,
             float* __restrict__ C, int M, int N, int K, int flags)
{
    extern __shared__ char smc[];
    const uint32_t sb = smem_to_u32(smc);
    const int tid = threadIdx.x, lane = tid & 31, warp = tid >> 5;
    const int wm = warp >> 2, wn = warp & 3;
    const int m0 = blockIdx.y * 128, n0 = blockIdx.x * 128;
    const int lda2 = K - kSplit;
    const int nkt = K >> 4;

    auto fill = [&](int kt) {
        const int s = kt & 3;
        const uint32_t as = sb + s * STG_;
        const uint32_t bs = as + 10240;
        const int k0 = kt << 4;
#pragma unroll
        for (int i = 0; i < 2; i++) {
            int ch = tid + 256 * i;
            int row = ch >> 2, kh = ch & 3;
            int k = k0 + kh * 4;
            const float* src = (k < kSplit)
                ? A  + (size_t)(m0 + row) * kSplit + k
                : A2 + (size_t)(m0 + row) * lda2 + (k - kSplit);
            cp16(as + row * 80 + kh * 16, src);
        }
#pragma unroll
        for (int i = 0; i < 2; i++) {
            int ch = tid + 256 * i;
            int row = ch >> 2, kh = ch & 3;
            cp16(bs + row * 80 + kh * 16, Bt + (size_t)(n0 + row) * K + k0 + kh * 4);
        }
    };

    float acc[4][4][4];
#pragma unroll
    for (int i = 0; i < 4; i++)
#pragma unroll
        for (int j = 0; j < 4; j++)
#pragma unroll
            for (int r = 0; r < 4; r++) acc[i][j][r] = 0.f;

    fill(0); cp_commit();
    fill(1); cp_commit();
    fill(2); cp_commit();

    const uint32_t aoff = (uint32_t)((wm * 64 + (lane & 15)) * 80 + (lane >> 4) * 16);
    const uint32_t boff = (uint32_t)((wn * 32 + (lane & 15)) * 80 + (lane >> 4) * 16);

    for (int kt = 0; kt < nkt; kt++) {
        cp_wait<2>();
        __syncthreads();
        if (kt + 3 < nkt) fill(kt + 3);
        cp_commit();
        const uint32_t as = sb + (kt & 3) * STG_;
        const uint32_t bs = as + 10240;
#pragma unroll
        for (int ks = 0; ks < 2; ks++) {
            uint32_t af[4][4], bf[2][4];
#pragma unroll
            for (int mi = 0; mi < 4; mi++)
                ldsm4(af[mi][0], af[mi][1], af[mi][2], af[mi][3],
                      as + aoff + mi * (16 * 80) + ks * 32);
#pragma unroll
            for (int nip = 0; nip < 2; nip++)
                ldsm4(bf[nip][0], bf[nip][1], bf[nip][2], bf[nip][3],
                      bs + boff + nip * (16 * 80) + ks * 32);
#pragma unroll
            for (int mi = 0; mi < 4; mi++)
#pragma unroll
                for (int ni = 0; ni < 4; ni++) {
                    const int nip = ni >> 1, o = ni & 1;
                    mma_tf32(acc[mi][ni], af[mi], bf[nip][o], bf[nip][o + 2]);
                }
        }
    }

    const int g = lane >> 2, t = lane & 3;
#pragma unroll
    for (int mi = 0; mi < 4; mi++) {
#pragma unroll
        for (int ni = 0; ni < 4; ni++) {
            const int r0 = m0 + wm * 64 + mi * 16 + g;
            const int cc = n0 + wn * 32 + ni * 8 + 2 * t;
            float2 v0 = make_float2(acc[mi][ni][0], acc[mi][ni][1]);
            float2 v1 = make_float2(acc[mi][ni][2], acc[mi][ni][3]);
            if (flags & 1) {
                float2 bb = *(const float2*)(bias + cc);
                v0.x += bb.x; v0.y += bb.y; v1.x += bb.x; v1.y += bb.y;
            }
            if (flags & 2) {
                v0.x = fmaxf(v0.x, 0.f); v0.y = fmaxf(v0.y, 0.f);
                v1.x = fmaxf(v1.x, 0.f); v1.y = fmaxf(v1.y, 0.f);
            }
            if (flags & 8) {
                v0.x = __uint_as_float(f2tf32(v0.x)); v0.y = __uint_as_float(f2tf32(v0.y));
                v1.x = __uint_as_float(f2tf32(v1.x)); v1.y = __uint_as_float(f2tf32(v1.y));
            }
            *(float2*)(C + (size_t)r0 * N + cc) = v0;
            *(float2*)(C + (size_t)(r0 + 8) * N + cc) = v1;
        }
    }
}

// ---------------- attention ---------------------------------------------------------
#define ATT_PAD 68
#define ATT_SMEM_FLOATS ((64 + 128 + 128) * ATT_PAD + 8 * 128)

__global__ __launch_bounds__(256)
void attn_kernel(const float* __restrict__ q, const float* __restrict__ k,
                 const float* __restrict__ v, const float* __restrict__ sbias,
                 float* __restrict__ ctx)
{
    extern __shared__ float sm[];
    float* Qs = sm;
    float* Ks = sm + 64 * ATT_PAD;
    float* Vs = Ks + 128 * ATT_PAD;
    float* probs = Vs + 128 * ATT_PAD;

    const int b = blockIdx.x / NH_;
    const int h = blockIdx.x % NH_;
    const int t0 = blockIdx.y * 64;
    const int tid = threadIdx.x;
    const int lane = tid & 31;
    const int warp = tid >> 5;
    const int hd = h * D_;

    for (int e = tid; e < 128 * 16; e += 256) {
        int s = e >> 4;
        int d4 = (e & 15) << 2;
        size_t gofs = ((size_t)(s * B_ + b)) * H_ + hd + d4;
        *(float4*)&Ks[s * ATT_PAD + d4] = *(const float4*)&k[gofs];
        *(float4*)&Vs[s * ATT_PAD + d4] = *(const float4*)&v[gofs];
    }
    for (int e = tid; e < 64 * 16; e += 256) {
        int r = e >> 4;
        int d4 = (e & 15) << 2;
        *(float4*)&Qs[r * ATT_PAD + d4] =
            *(const float4*)&q[((size_t)((t0 + r) * B_ + b)) * H_ + hd + d4];
    }
    __syncthreads();

    const float scale = 0.125f;
    float* pw = probs + warp * 128;

    for (int r8 = 0; r8 < 8; r8++) {
        int row = warp * 8 + r8;
        const float4* qrow = (const float4*)&Qs[row * ATT_PAD];
        const float4* k0p = (const float4*)&Ks[(lane) * ATT_PAD];
        const float4* k1p = (const float4*)&Ks[(lane + 32) * ATT_PAD];
        const float4* k2p = (const float4*)&Ks[(lane + 64) * ATT_PAD];
        const float4* k3p = (const float4*)&Ks[(lane + 96) * ATT_PAD];
        float a0 = 0.f, a1 = 0.f, a2 = 0.f, a3 = 0.f;
#pragma unroll
        for (int d4 = 0; d4 < 16; d4++) {
            float4 qv = qrow[d4];
            float4 kv;
            kv = k0p[d4]; a0 += qv.x*kv.x + qv.y*kv.y + qv.z*kv.z + qv.w*kv.w;
            kv = k1p[d4]; a1 += qv.x*kv.x + qv.y*kv.y + qv.z*kv.z + qv.w*kv.w;
            kv = k2p[d4]; a2 += qv.x*kv.x + qv.y*kv.y + qv.z*kv.z + qv.w*kv.w;
            kv = k3p[d4]; a3 += qv.x*kv.x + qv.y*kv.y + qv.z*kv.z + qv.w*kv.w;
        }
        a0 = a0 * scale + sbias[b * S_ + lane];
        a1 = a1 * scale + sbias[b * S_ + lane + 32];
        a2 = a2 * scale + sbias[b * S_ + lane + 64];
        a3 = a3 * scale + sbias[b * S_ + lane + 96];

        float mx = fmaxf(fmaxf(a0, a1), fmaxf(a2, a3));
#pragma unroll
        for (int off = 16; off; off >>= 1)
            mx = fmaxf(mx, __shfl_xor_sync(0xffffffffu, mx, off));
        float e0 = __expf(a0 - mx), e1 = __expf(a1 - mx);
        float e2 = __expf(a2 - mx), e3 = __expf(a3 - mx);
        float ssum = e0 + e1 + e2 + e3;
#pragma unroll
        for (int off = 16; off; off >>= 1)
            ssum += __shfl_xor_sync(0xffffffffu, ssum, off);
        float inv = 1.f / ssum;

        pw[lane] = e0 * inv; pw[lane + 32] = e1 * inv;
        pw[lane + 64] = e2 * inv; pw[lane + 96] = e3 * inv;
        __syncwarp();

        float c0 = 0.f, c1 = 0.f;
#pragma unroll 4
        for (int s = 0; s < 128; s++) {
            float p = pw[s];
            c0 += p * Vs[s * ATT_PAD + lane];
            c1 += p * Vs[s * ATT_PAD + lane + 32];
        }
        float* crow = &ctx[((size_t)((t0 + row) * B_ + b)) * H_ + hd];
        crow[lane] = __uint_as_float(f2tf32(c0));
        crow[lane + 32] = __uint_as_float(f2tf32(c1));
        __syncwarp();
    }
}

// ---------------- persistent LSTM recurrence (fp16 MMA) -----------------------------
// 128 CTAs, 1/SM. CTA n owns hidden cols [n*8, n*8+8) => 32 g-cols (4 gates x 8).
// Whh slice in fp16 (64KB) resident in smem; h is fp16 — whole h (64KB) staged in
// smem per step in 8 tile buffers (no ring reuse), fills all issued up-front.
// fp16 m16n8k16 mma (same 10-bit mantissa as tf32 for normal values => precision
// neutral). Barrier: red.release/ld.acquire (no gpu-fence => no per-step L1D flush).
#define LR_BPITCH 2064                       // 1024 halves + 16B pad (odd 16B units)
#define LR_APITCH 272                        // 128 halves + 16B pad
#define LR_ATILE  (32 * LR_APITCH)           // 8704
#define LR_AOFF   (32 * LR_BPITCH)           // 66048
#define LR_POFF   (LR_AOFF + 8 * LR_ATILE)   // 135680
#define LR_SMEM   (LR_POFF + 8 * 256 * 4)    // 143872

__global__ __launch_bounds__(256, 1)
void lstm_persist(const float* __restrict__ gpre, const __half* __restrict__ WhhH,
                  __half* __restrict__ hbufH, float* __restrict__ out,
                  float* __restrict__ cf, float* __restrict__ hf,
                  int* __restrict__ ctr, int has_tail)
{
    extern __shared__ char smc[];
    const uint32_t sb = smem_to_u32(smc);
    const uint32_t Bs = sb;
    const uint32_t As = sb + LR_AOFF;
    float* part = (float*)(smc + LR_POFF);
    const int tid = threadIdx.x, lane = tid & 31, warp = tid >> 5;
    const int c0 = blockIdx.x * 8;

    // one-time: fp16 Whh slice -> smem. g-row (gate*8+j) = WhhH row gate*1024+c0+j.
#pragma unroll 4
    for (int i = 0; i < 16; i++) {
        int id = tid + 256 * i;                  // 4096 chunks of 16B
        int row = id >> 7, ch = id & 127;
        int gate = row >> 3, j = row & 7;
        cp16(Bs + row * LR_BPITCH + ch * 16,
             WhhH + (size_t)(gate * H_ + c0 + j) * H_ + ch * 8);
    }
    cp_commit(); cp_wait<0>(); __syncthreads();

    const int wm = warp & 1, wn = (warp >> 1) & 1, wk = warp >> 2;
    const uint32_t aoff = (uint32_t)((wm * 16 + (lane & 15)) * LR_APITCH + (lane >> 4) * 16);
    const uint32_t boff = (uint32_t)((wn * 16 + (lane & 15)) * LR_BPITCH + (lane >> 4) * 16);
    const int row_e = tid >> 3, j_e = tid & 7;   // epilogue: batch row, hidden col
    const int idx_h = row_e * H_ + c0 + j_e;

    float creg = 0.f;
    float gpv[4];
#pragma unroll
    for (int gi = 0; gi < 4; gi++)
        gpv[gi] = __ldg(gpre + (size_t)row_e * (4 * H_) + gi * H_ + c0 + j_e);

    for (int t = 0; t < T_; t++) {
        const __half* hin = hbufH + (t & 1) * (B_ * H_);
        __half* hout = hbufH + (1 - (t & 1)) * (B_ * H_);

        // deferred barrier wait (acquire)
        if (t > 0) {
            if (tid == 0) {
                int v;
                do {
                    asm volatile("ld.acquire.gpu.global.s32 %0, [%1];"
                                 : "=r"(v) : "l"(ctr + t - 1) : "memory");
                    if (v < 128) __nanosleep(16);
                } while (v < 128);
            }
            __syncthreads();
        }

        // stream whole h: 8 tiles of 128 halves, all fills up-front (8 groups)
#define LR_FILL(kt_) do { \
            const uint32_t as_f = As + (kt_) * LR_ATILE; \
            _Pragma("unroll") \
            for (int i_ = 0; i_ < 2; i_++) { \
                int id_ = tid + 256 * i_; \
                int row_ = id_ >> 4, kh_ = id_ & 15; \
                cp16(as_f + row_ * LR_APITCH + kh_ * 16, \
                     hin + row_ * H_ + (kt_) * 128 + kh_ * 8); \
            } \
            cp_commit(); \
        } while (0)
        LR_FILL(0); LR_FILL(1); LR_FILL(2); LR_FILL(3);
        LR_FILL(4); LR_FILL(5); LR_FILL(6); LR_FILL(7);

        float acc[2][4];
#pragma unroll
        for (int i = 0; i < 2; i++)
#pragma unroll
            for (int r = 0; r < 4; r++) acc[i][r] = 0.f;

#define LR_STEP(kt_, w_) do { \
            cp_wait<w_>(); \
            __syncthreads(); \
            if (((kt_) >> 2) == wk) { \
                const uint32_t as_ = As + (kt_) * LR_ATILE + aoff; \
                const uint32_t bk_ = Bs + boff + (kt_) * 256; \
                _Pragma("unroll") \
                for (int s8 = 0; s8 < 8; s8++) { \
                    uint32_t af[4], b0, b1, b2, b3; \
                    ldsm4(af[0], af[1], af[2], af[3], as_ + s8 * 32); \
                    ldsm4(b0, b1, b2, b3, bk_ + s8 * 32); \
                    mma_f16(acc[0], af, b0, b2); \
                    mma_f16(acc[1], af, b1, b3); \
                } \
            } \
        } while (0)
        LR_STEP(0, 7); LR_STEP(1, 6); LR_STEP(2, 5); LR_STEP(3, 4);
        LR_STEP(4, 3); LR_STEP(5, 2); LR_STEP(6, 1); LR_STEP(7, 0);

        // prefetch next step's gate bias early (overlaps epilogue + barrier)
        float gpn[4] = {0.f, 0.f, 0.f, 0.f};
        if (t + 1 < T_) {
            const float* gp1 = gpre + (size_t)(t + 1) * B_ * 4 * H_;
#pragma unroll
            for (int gi = 0; gi < 4; gi++)
                gpn[gi] = __ldg(gp1 + (size_t)row_e * (4 * H_) + gi * H_ + c0 + j_e);
        }

        // store per-warp partials [16x16]
        {
            const int g = lane >> 2, tq = lane & 3;
            float* pw = part + warp * 256;
#pragma unroll
            for (int ni = 0; ni < 2; ni++) {
                *(float2*)&pw[g * 16 + ni * 8 + 2 * tq] = make_float2(acc[ni][0], acc[ni][1]);
                *(float2*)&pw[(g + 8) * 16 + ni * 8 + 2 * tq] = make_float2(acc[ni][2], acc[ni][3]);
            }
        }
        __syncthreads();

        // combine k-halves + gpre; gates; state update (c carried in register)
        {
            float gv[4];
#pragma unroll
            for (int gate = 0; gate < 4; gate++) {
                int ncol = gate * 8 + j_e;
                int w0 = (row_e >> 4) | ((ncol >> 4) << 1);
                int idx = (row_e & 15) * 16 + (ncol & 15);
                gv[gate] = part[w0 * 256 + idx] + part[(w0 + 4) * 256 + idx] + gpv[gate];
            }
            float iv = sigmoidf_(gv[0]);
            float jv = tanhf(gv[1]);
            float fv = sigmoidf_(gv[2]);
            float ov = sigmoidf_(gv[3]);
            float nc = fv * creg + iv * jv;
            float nh = ov * nc;                       // THUMT LSTMCell: activation=None
            creg = nc;
            __stwt(&out[(size_t)t * B_ * H_ + idx_h], nh);
            hout[idx_h] = __float2half(nh);
            if (has_tail && t == T_ - 1) { cf[idx_h] = nc; hf[idx_h] = nh; }
        }
#pragma unroll
        for (int gi = 0; gi < 4; gi++) gpv[gi] = gpn[gi];

        // barrier arrival (release; no gpu fence -> no L1D flush)
        __syncthreads();
        if (tid == 0)
            asm volatile("red.release.gpu.global.add.s32 [%0], 1;"
                         :: "l"(ctr + t) : "memory");
    }
}

// ---------------- launch ------------------------------------------------------------
extern "C" void kernel_launch(void* const* d_in, const int* in_sizes, int n_in,
                              void* d_out, int out_size)
{
    (void)in_sizes; (void)n_in;
    const float* x  = (const float*)d_in[0];
    const float* sb = (const float*)d_in[1];
    const float* mem = (const float*)d_in[3];
    const float* Wq = (const float*)d_in[4];  const float* bq = (const float*)d_in[5];
    const float* Wk = (const float*)d_in[6];  const float* bk = (const float*)d_in[7];
    const float* Wv = (const float*)d_in[8];  const float* bv = (const float*)d_in[9];
    const float* Wo = (const float*)d_in[10]; const float* bo = (const float*)d_in[11];
    const float* W1 = (const float*)d_in[12]; const float* b1 = (const float*)d_in[13];
    const float* W2 = (const float*)d_in[14]; const float* b2 = (const float*)d_in[15];
    const float* Wg = (const float*)d_in[16]; const float* bg = (const float*)d_in[17];
    float* out = (float*)d_out;

    float *q, *k, *v, *ctx, *attn, *ffnh, *ffnx, *gpre, *hbuf, *cbuf, *wT, *xr, *memr;
    int* ctr;
    cudaGetSymbolAddress((void**)&q,    g_q);
    cudaGetSymbolAddress((void**)&k,    g_k);
    cudaGetSymbolAddress((void**)&v,    g_v);
    cudaGetSymbolAddress((void**)&ctx,  g_ctx);
    cudaGetSymbolAddress((void**)&attn, g_attn);
    cudaGetSymbolAddress((void**)&ffnh, g_ffnh);
    cudaGetSymbolAddress((void**)&ffnx, g_ffnx);
    cudaGetSymbolAddress((void**)&gpre, g_gpre);
    cudaGetSymbolAddress((void**)&hbuf, g_hbuf);
    cudaGetSymbolAddress((void**)&cbuf, g_cbuf);
    cudaGetSymbolAddress((void**)&wT,   g_wT);
    cudaGetSymbolAddress((void**)&xr,   g_xr);
    cudaGetSymbolAddress((void**)&memr, g_memr);
    cudaGetSymbolAddress((void**)&ctr,  g_ctr);

    float* WqT = wT;
    float* WkT = wT + (size_t)1 * MM_;
    float* WvT = wT + (size_t)2 * MM_;
    float* WoT = wT + (size_t)3 * MM_;
    float* W1T = wT + (size_t)4 * MM_;
    float* W2T = wT + (size_t)8 * MM_;
    float* WgT = wT + (size_t)12 * MM_;
    __half* WhhH = (__half*)(wT + (size_t)20 * MM_);

    dim3 blk(256);

    // prepass: weight transpose + round; activation rounding
    transpose_tf32<<<dim3(H_ / 32, H_ / 32), blk>>>(Wq, WqT, H_, H_);
    transpose_tf32<<<dim3(H_ / 32, H_ / 32), blk>>>(Wk, WkT, H_, H_);
    transpose_tf32<<<dim3(H_ / 32, H_ / 32), blk>>>(Wv, WvT, H_, H_);
    transpose_tf32<<<dim3(H_ / 32, H_ / 32), blk>>>(Wo, WoT, H_, H_);
    transpose_tf32<<<dim3(F_ / 32, H_ / 32), blk>>>(W1, W1T, H_, F_);
    transpose_tf32<<<dim3(H_ / 32, F_ / 32), blk>>>(W2, W2T, F_, H_);
    transpose_tf32<<<dim3(F_ / 32, (2 * H_) / 32), blk>>>(Wg, WgT, 2 * H_, F_);
    transpose_f16<<<dim3(F_ / 32, H_ / 32), blk>>>(
        Wg + (size_t)2 * H_ * 4 * H_, WhhH, H_, F_);
    round_tf32<<<1024, blk>>>(x, xr, T_ * B_ * H_);
    round_tf32<<<1024, blk>>>(mem, memr, S_ * B_ * H_);

    const int GSM = 4 * STG_;   // 81920
    cudaFuncSetAttribute(mm_gemm, cudaFuncAttributeMaxDynamicSharedMemorySize, GSM);
    cudaFuncSetAttribute(lstm_persist, cudaFuncAttributeMaxDynamicSharedMemorySize, LR_SMEM);

    // projections
    mm_gemm<<<dim3(H_ / 128, (T_ * B_) / 128), blk, GSM>>>(
        xr, xr, H_, WqT, bq, q, T_ * B_, H_, H_, 1);
    mm_gemm<<<dim3(H_ / 128, (S_ * B_) / 128), blk, GSM>>>(
        memr, memr, H_, WkT, bk, k, S_ * B_, H_, H_, 1);
    mm_gemm<<<dim3(H_ / 128, (S_ * B_) / 128), blk, GSM>>>(
        memr, memr, H_, WvT, bv, v, S_ * B_, H_, H_, 1);

    // attention
    size_t attn_smem = (size_t)ATT_SMEM_FLOATS * sizeof(float);
    cudaFuncSetAttribute(attn_kernel, cudaFuncAttributeMaxDynamicSharedMemorySize,
                         (int)attn_smem);
    attn_kernel<<<dim3(B_ * NH_, T_ / 64), blk, attn_smem>>>(q, k, v, sb, ctx);

    // output projection
    mm_gemm<<<dim3(H_ / 128, (T_ * B_) / 128), blk, GSM>>>(
        ctx, ctx, H_, WoT, bo, attn, T_ * B_, H_, H_, 1 | 8);

    // feed-forward
    mm_gemm<<<dim3(F_ / 128, (T_ * B_) / 128), blk, GSM>>>(
        xr, xr, H_, W1T, b1, ffnh, T_ * B_, F_, H_, 1 | 2 | 8);
    mm_gemm<<<dim3(H_ / 128, (T_ * B_) / 128), blk, GSM>>>(
        ffnh, ffnh, F_, W2T, b2, ffnx, T_ * B_, H_, F_, 1 | 8);

    // gate precompute (fused dual-source K=2048): gpre = [ffnx|attn] @ WgT^T + bg
    mm_gemm<<<dim3((4 * H_) / 128, (T_ * B_) / 128), blk, GSM>>>(
        ffnx, attn, H_, WgT, bg, gpre, T_ * B_, 4 * H_, 2 * H_, 1);

    // recurrence: one persistent launch (fp16 h / Whh)
    init_state<<<(2 * B_ * H_ + 255) / 256, 256>>>(hbuf, cbuf, ctr);
    int has_tail = out_size >= T_ * B_ * H_ + 2 * B_ * H_;
    float* cf = out + (size_t)T_ * B_ * H_;
    float* hf = cf + B_ * H_;
    lstm_persist<<<128, blk, LR_SMEM>>>(gpre, (const __half*)WhhH, (__half*)hbuf,
                                        out, cf, hf, ctr, has_tail);
}

// round 15
// speedup vs baseline: 1.6148x; 1.4464x over previous
#include <cuda_runtime.h>
#include <cuda_fp16.h>
#include <math.h>
#include <stdint.h>

#define T_ 256
#define S_ 128
#define B_ 32
#define H_ 1024
#define NH_ 16
#define D_ 64
#define F_ 4096

// ---------------- scratch (static device globals; no allocation) ----------------
__device__ float g_q[(size_t)T_ * B_ * H_];
__device__ float g_k[(size_t)S_ * B_ * H_];
__device__ float g_v[(size_t)S_ * B_ * H_];
__device__ float g_ctx[(size_t)T_ * B_ * H_];    // used as __half
__device__ float g_attn[(size_t)T_ * B_ * H_];   // used as __half
__device__ float g_ffnh[(size_t)T_ * B_ * F_];   // used as __half
__device__ float g_ffnx[(size_t)T_ * B_ * H_];   // used as __half
__device__ float g_gpre[(size_t)T_ * B_ * 4 * H_];
__device__ float g_hbuf[2 * B_ * H_];            // used as __half[2][B*H]
__device__ float g_cbuf[B_ * H_];
__device__ float g_xr[(size_t)T_ * B_ * H_];     // used as __half (xh)
__device__ float g_memr[(size_t)S_ * B_ * H_];   // used as __half (memh)
__device__ int   g_ctr[T_];
// fp16 weights packed into g_wT (as __half): Wq 0, Wk 1M, Wv 2M, Wo 3M, W1 4M,
// W2 8M, Wg 12M, Whh 20M  (halves)
#define MM_ (1024 * 1024)
__device__ float g_wT[(size_t)24 * MM_];

// ---------------- PTX helpers ----------------------------------------------------
__device__ __forceinline__ uint32_t smem_to_u32(const void* p) {
    uint32_t a;
    asm("{ .reg .u64 t; cvta.to.shared.u64 t, %1; cvt.u32.u64 %0, t; }" : "=r"(a) : "l"(p));
    return a;
}
__device__ __forceinline__ void cp16(uint32_t s, const void* g) {
    asm volatile("cp.async.cg.shared.global [%0], [%1], 16;\n" :: "r"(s), "l"(g));
}
__device__ __forceinline__ void cp_commit() { asm volatile("cp.async.commit_group;\n"); }
template<int N> __device__ __forceinline__ void cp_wait() {
    asm volatile("cp.async.wait_group %0;\n" :: "n"(N));
}
__device__ __forceinline__ void ldsm4(uint32_t& r0, uint32_t& r1, uint32_t& r2,
                                      uint32_t& r3, uint32_t addr) {
    asm volatile("ldmatrix.sync.aligned.m8n8.x4.shared.b16 {%0,%1,%2,%3}, [%4];"
                 : "=r"(r0), "=r"(r1), "=r"(r2), "=r"(r3) : "r"(addr));
}
__device__ __forceinline__ void mma_f16(float (&d)[4], const uint32_t (&a)[4],
                                        uint32_t b0, uint32_t b1) {
    asm volatile(
        "mma.sync.aligned.m16n8k16.row.col.f32.f16.f16.f32 "
        "{%0,%1,%2,%3}, {%4,%5,%6,%7}, {%8,%9}, {%0,%1,%2,%3};\n"
        : "+f"(d[0]), "+f"(d[1]), "+f"(d[2]), "+f"(d[3])
        : "r"(a[0]), "r"(a[1]), "r"(a[2]), "r"(a[3]), "r"(b0), "r"(b1));
}
__device__ __forceinline__ float sigmoidf_(float x) { return 1.f / (1.f + __expf(-x)); }

// ---------------- prepass kernels -------------------------------------------------
__global__ __launch_bounds__(256)
void transpose_f16(const float* __restrict__ in, __half* __restrict__ out, int R, int C)
{
    __shared__ float t[32][33];
    const int bx = blockIdx.x * 32;
    const int by = blockIdx.y * 32;
    const int tx = threadIdx.x & 31;
    const int ty = threadIdx.x >> 5;
#pragma unroll
    for (int i = 0; i < 4; i++)
        t[ty + 8 * i][tx] = in[(size_t)(by + ty + 8 * i) * C + bx + tx];
    __syncthreads();
#pragma unroll
    for (int i = 0; i < 4; i++)
        out[(size_t)(bx + ty + 8 * i) * R + by + tx] = __float2half(t[tx][ty + 8 * i]);
}

__global__ __launch_bounds__(256)
void round_f16(const float* __restrict__ in, __half* __restrict__ out, int n)
{
    int i = blockIdx.x * 256 + threadIdx.x;
    for (; i < n; i += gridDim.x * 256)
        out[i] = __float2half(in[i]);
}

__global__ void init_state(float* h, float* cc, int* ctr)
{
    int i = blockIdx.x * 256 + threadIdx.x;
    if (i < 2 * B_ * H_) h[i] = 0.f;
    if (i < B_ * H_) cc[i] = 0.f;
    if (i < T_) ctr[i] = 0;
}

// ---------------- fp16 mma GEMM: C[MxN] = A @ Bt^T ---------------------------------
// A: [M][K] fp16, dual-source rows [A(kSplit) | A2(K-kSplit)]; Bt: [N][K] fp16.
// flags: 1=bias(fp32), 2=relu, 16=fp16 output (else fp32).
// 128x128 tile, K-tile=32 halves, 4-stage cp.async, m16n8k16 fragments.
#define STG_ 20480   // A 128*80 + B 128*80 (rows of 32 halves=64B + 16B pad)
__global__ __launch_bounds__(256, 2)
void mm_gemm(const __half* __restrict__ A, const __half* __restrict__ A2, int kSplit,
             const __half* __restrict__ Bt, const float* __restrict__ bias,
             void* __restrict__ Cout, int M, int N, int K, int flags)
{
    extern __shared__ char smc[];
    const uint32_t sb = smem_to_u32(smc);
    const int tid = threadIdx.x, lane = tid & 31, warp = tid >> 5;
    const int wm = warp >> 2, wn = warp & 3;
    const int m0 = blockIdx.y * 128, n0 = blockIdx.x * 128;
    const int lda2 = K - kSplit;
    const int nkt = K >> 5;

    auto fill = [&](int kt) {
        const int s = kt & 3;
        const uint32_t as = sb + s * STG_;
        const uint32_t bs = as + 10240;
        const int k0 = kt << 5;
#pragma unroll
        for (int i = 0; i < 2; i++) {
            int ch = tid + 256 * i;
            int row = ch >> 2, kh = ch & 3;
            int k = k0 + kh * 8;
            const __half* src = (k < kSplit)
                ? A  + (size_t)(m0 + row) * kSplit + k
                : A2 + (size_t)(m0 + row) * lda2 + (k - kSplit);
            cp16(as + row * 80 + kh * 16, src);
        }
#pragma unroll
        for (int i = 0; i < 2; i++) {
            int ch = tid + 256 * i;
            int row = ch >> 2, kh = ch & 3;
            cp16(bs + row * 80 + kh * 16, Bt + (size_t)(n0 + row) * K + k0 + kh * 8);
        }
    };

    float acc[4][4][4];
#pragma unroll
    for (int i = 0; i < 4; i++)
#pragma unroll
        for (int j = 0; j < 4; j++)
#pragma unroll
            for (int r = 0; r < 4; r++) acc[i][j][r] = 0.f;

    fill(0); cp_commit();
    fill(1); cp_commit();
    fill(2); cp_commit();

    const uint32_t aoff = (uint32_t)((wm * 64 + (lane & 15)) * 80 + (lane >> 4) * 16);
    const uint32_t boff = (uint32_t)((wn * 32 + (lane & 15)) * 80 + (lane >> 4) * 16);

    for (int kt = 0; kt < nkt; kt++) {
        cp_wait<2>();
        __syncthreads();
        if (kt + 3 < nkt) fill(kt + 3);
        cp_commit();
        const uint32_t as = sb + (kt & 3) * STG_;
        const uint32_t bs = as + 10240;
#pragma unroll
        for (int ks = 0; ks < 2; ks++) {       // two k16 halves of the 32-half tile
            uint32_t af[4][4], bf[2][4];
#pragma unroll
            for (int mi = 0; mi < 4; mi++)
                ldsm4(af[mi][0], af[mi][1], af[mi][2], af[mi][3],
                      as + aoff + mi * (16 * 80) + ks * 32);
#pragma unroll
            for (int nip = 0; nip < 2; nip++)
                ldsm4(bf[nip][0], bf[nip][1], bf[nip][2], bf[nip][3],
                      bs + boff + nip * (16 * 80) + ks * 32);
#pragma unroll
            for (int mi = 0; mi < 4; mi++)
#pragma unroll
                for (int ni = 0; ni < 4; ni++) {
                    const int nip = ni >> 1, o = ni & 1;
                    mma_f16(acc[mi][ni], af[mi], bf[nip][o], bf[nip][o + 2]);
                }
        }
    }

    const int g = lane >> 2, t = lane & 3;
#pragma unroll
    for (int mi = 0; mi < 4; mi++) {
#pragma unroll
        for (int ni = 0; ni < 4; ni++) {
            const int r0 = m0 + wm * 64 + mi * 16 + g;
            const int cc = n0 + wn * 32 + ni * 8 + 2 * t;
            float2 v0 = make_float2(acc[mi][ni][0], acc[mi][ni][1]);
            float2 v1 = make_float2(acc[mi][ni][2], acc[mi][ni][3]);
            if (flags & 1) {
                float2 bb = *(const float2*)(bias + cc);
                v0.x += bb.x; v0.y += bb.y; v1.x += bb.x; v1.y += bb.y;
            }
            if (flags & 2) {
                v0.x = fmaxf(v0.x, 0.f); v0.y = fmaxf(v0.y, 0.f);
                v1.x = fmaxf(v1.x, 0.f); v1.y = fmaxf(v1.y, 0.f);
            }
            if (flags & 16) {
                __half* C = (__half*)Cout;
                *(__half2*)(C + (size_t)r0 * N + cc) = __floats2half2_rn(v0.x, v0.y);
                *(__half2*)(C + (size_t)(r0 + 8) * N + cc) = __floats2half2_rn(v1.x, v1.y);
            } else {
                float* C = (float*)Cout;
                *(float2*)(C + (size_t)r0 * N + cc) = v0;
                *(float2*)(C + (size_t)(r0 + 8) * N + cc) = v1;
            }
        }
    }
}

// ---------------- attention (fp32 in, fp16 ctx out) ---------------------------------
#define ATT_PAD 68
#define ATT_SMEM_FLOATS ((64 + 128 + 128) * ATT_PAD + 8 * 128)

__global__ __launch_bounds__(256)
void attn_kernel(const float* __restrict__ q, const float* __restrict__ k,
                 const float* __restrict__ v, const float* __restrict__ sbias,
                 __half* __restrict__ ctx)
{
    extern __shared__ float sm[];
    float* Qs = sm;
    float* Ks = sm + 64 * ATT_PAD;
    float* Vs = Ks + 128 * ATT_PAD;
    float* probs = Vs + 128 * ATT_PAD;

    const int b = blockIdx.x / NH_;
    const int h = blockIdx.x % NH_;
    const int t0 = blockIdx.y * 64;
    const int tid = threadIdx.x;
    const int lane = tid & 31;
    const int warp = tid >> 5;
    const int hd = h * D_;

    for (int e = tid; e < 128 * 16; e += 256) {
        int s = e >> 4;
        int d4 = (e & 15) << 2;
        size_t gofs = ((size_t)(s * B_ + b)) * H_ + hd + d4;
        *(float4*)&Ks[s * ATT_PAD + d4] = *(const float4*)&k[gofs];
        *(float4*)&Vs[s * ATT_PAD + d4] = *(const float4*)&v[gofs];
    }
    for (int e = tid; e < 64 * 16; e += 256) {
        int r = e >> 4;
        int d4 = (e & 15) << 2;
        *(float4*)&Qs[r * ATT_PAD + d4] =
            *(const float4*)&q[((size_t)((t0 + r) * B_ + b)) * H_ + hd + d4];
    }
    __syncthreads();

    const float scale = 0.125f;
    float* pw = probs + warp * 128;

    for (int r8 = 0; r8 < 8; r8++) {
        int row = warp * 8 + r8;
        const float4* qrow = (const float4*)&Qs[row * ATT_PAD];
        const float4* k0p = (const float4*)&Ks[(lane) * ATT_PAD];
        const float4* k1p = (const float4*)&Ks[(lane + 32) * ATT_PAD];
        const float4* k2p = (const float4*)&Ks[(lane + 64) * ATT_PAD];
        const float4* k3p = (const float4*)&Ks[(lane + 96) * ATT_PAD];
        float a0 = 0.f, a1 = 0.f, a2 = 0.f, a3 = 0.f;
#pragma unroll
        for (int d4 = 0; d4 < 16; d4++) {
            float4 qv = qrow[d4];
            float4 kv;
            kv = k0p[d4]; a0 += qv.x*kv.x + qv.y*kv.y + qv.z*kv.z + qv.w*kv.w;
            kv = k1p[d4]; a1 += qv.x*kv.x + qv.y*kv.y + qv.z*kv.z + qv.w*kv.w;
            kv = k2p[d4]; a2 += qv.x*kv.x + qv.y*kv.y + qv.z*kv.z + qv.w*kv.w;
            kv = k3p[d4]; a3 += qv.x*kv.x + qv.y*kv.y + qv.z*kv.z + qv.w*kv.w;
        }
        a0 = a0 * scale + sbias[b * S_ + lane];
        a1 = a1 * scale + sbias[b * S_ + lane + 32];
        a2 = a2 * scale + sbias[b * S_ + lane + 64];
        a3 = a3 * scale + sbias[b * S_ + lane + 96];

        float mx = fmaxf(fmaxf(a0, a1), fmaxf(a2, a3));
#pragma unroll
        for (int off = 16; off; off >>= 1)
            mx = fmaxf(mx, __shfl_xor_sync(0xffffffffu, mx, off));
        float e0 = __expf(a0 - mx), e1 = __expf(a1 - mx);
        float e2 = __expf(a2 - mx), e3 = __expf(a3 - mx);
        float ssum = e0 + e1 + e2 + e3;
#pragma unroll
        for (int off = 16; off; off >>= 1)
            ssum += __shfl_xor_sync(0xffffffffu, ssum, off);
        float inv = 1.f / ssum;

        pw[lane] = e0 * inv; pw[lane + 32] = e1 * inv;
        pw[lane + 64] = e2 * inv; pw[lane + 96] = e3 * inv;
        __syncwarp();

        float c0 = 0.f, c1 = 0.f;
#pragma unroll 4
        for (int s = 0; s < 128; s++) {
            float p = pw[s];
            c0 += p * Vs[s * ATT_PAD + lane];
            c1 += p * Vs[s * ATT_PAD + lane + 32];
        }
        __half* crow = &ctx[((size_t)((t0 + row) * B_ + b)) * H_ + hd];
        crow[lane] = __float2half(c0);
        crow[lane + 32] = __float2half(c1);
        __syncwarp();
    }
}

// ---------------- persistent LSTM recurrence (fp16 MMA) -----------------------------
#define LR_BPITCH 2064
#define LR_APITCH 272
#define LR_ATILE  (32 * LR_APITCH)
#define LR_AOFF   (32 * LR_BPITCH)
#define LR_POFF   (LR_AOFF + 8 * LR_ATILE)
#define LR_SMEM   (LR_POFF + 8 * 256 * 4)

__global__ __launch_bounds__(256, 1)
void lstm_persist(const float* __restrict__ gpre, const __half* __restrict__ WhhH,
                  __half* __restrict__ hbufH, float* __restrict__ out,
                  float* __restrict__ cf, float* __restrict__ hf,
                  int* __restrict__ ctr, int has_tail)
{
    extern __shared__ char smc[];
    const uint32_t sb = smem_to_u32(smc);
    const uint32_t Bs = sb;
    const uint32_t As = sb + LR_AOFF;
    float* part = (float*)(smc + LR_POFF);
    const int tid = threadIdx.x, lane = tid & 31, warp = tid >> 5;
    const int c0 = blockIdx.x * 8;

#pragma unroll 4
    for (int i = 0; i < 16; i++) {
        int id = tid + 256 * i;
        int row = id >> 7, ch = id & 127;
        int gate = row >> 3, j = row & 7;
        cp16(Bs + row * LR_BPITCH + ch * 16,
             WhhH + (size_t)(gate * H_ + c0 + j) * H_ + ch * 8);
    }
    cp_commit(); cp_wait<0>(); __syncthreads();

    const int wm = warp & 1, wn = (warp >> 1) & 1, wk = warp >> 2;
    const uint32_t aoff = (uint32_t)((wm * 16 + (lane & 15)) * LR_APITCH + (lane >> 4) * 16);
    const uint32_t boff = (uint32_t)((wn * 16 + (lane & 15)) * LR_BPITCH + (lane >> 4) * 16);
    const int row_e = tid >> 3, j_e = tid & 7;
    const int idx_h = row_e * H_ + c0 + j_e;

    float creg = 0.f;
    float gpv[4];
#pragma unroll
    for (int gi = 0; gi < 4; gi++)
        gpv[gi] = __ldg(gpre + (size_t)row_e * (4 * H_) + gi * H_ + c0 + j_e);

    for (int t = 0; t < T_; t++) {
        const __half* hin = hbufH + (t & 1) * (B_ * H_);
        __half* hout = hbufH + (1 - (t & 1)) * (B_ * H_);

        if (t > 0) {
            if (tid == 0) {
                int v;
                do {
                    asm volatile("ld.acquire.gpu.global.s32 %0, [%1];"
                                 : "=r"(v) : "l"(ctr + t - 1) : "memory");
                    if (v < 128) __nanosleep(16);
                } while (v < 128);
            }
            __syncthreads();
        }

#define LR_FILL(kt_) do { \
            const uint32_t as_f = As + (kt_) * LR_ATILE; \
            _Pragma("unroll") \
            for (int i_ = 0; i_ < 2; i_++) { \
                int id_ = tid + 256 * i_; \
                int row_ = id_ >> 4, kh_ = id_ & 15; \
                cp16(as_f + row_ * LR_APITCH + kh_ * 16, \
                     hin + row_ * H_ + (kt_) * 128 + kh_ * 8); \
            } \
            cp_commit(); \
        } while (0)
        LR_FILL(0); LR_FILL(1); LR_FILL(2); LR_FILL(3);
        LR_FILL(4); LR_FILL(5); LR_FILL(6); LR_FILL(7);

        float acc[2][4];
#pragma unroll
        for (int i = 0; i < 2; i++)
#pragma unroll
            for (int r = 0; r < 4; r++) acc[i][r] = 0.f;

#define LR_STEP(kt_, w_) do { \
            cp_wait<w_>(); \
            __syncthreads(); \
            if (((kt_) >> 2) == wk) { \
                const uint32_t as_ = As + (kt_) * LR_ATILE + aoff; \
                const uint32_t bk_ = Bs + boff + (kt_) * 256; \
                _Pragma("unroll") \
                for (int s8 = 0; s8 < 8; s8++) { \
                    uint32_t af[4], b0, b1, b2, b3; \
                    ldsm4(af[0], af[1], af[2], af[3], as_ + s8 * 32); \
                    ldsm4(b0, b1, b2, b3, bk_ + s8 * 32); \
                    mma_f16(acc[0], af, b0, b2); \
                    mma_f16(acc[1], af, b1, b3); \
                } \
            } \
        } while (0)
        LR_STEP(0, 7); LR_STEP(1, 6); LR_STEP(2, 5); LR_STEP(3, 4);
        LR_STEP(4, 3); LR_STEP(5, 2); LR_STEP(6, 1); LR_STEP(7, 0);

        float gpn[4] = {0.f, 0.f, 0.f, 0.f};
        if (t + 1 < T_) {
            const float* gp1 = gpre + (size_t)(t + 1) * B_ * 4 * H_;
#pragma unroll
            for (int gi = 0; gi < 4; gi++)
                gpn[gi] = __ldg(gp1 + (size_t)row_e * (4 * H_) + gi * H_ + c0 + j_e);
        }

        {
            const int g = lane >> 2, tq = lane & 3;
            float* pw = part + warp * 256;
#pragma unroll
            for (int ni = 0; ni < 2; ni++) {
                *(float2*)&pw[g * 16 + ni * 8 + 2 * tq] = make_float2(acc[ni][0], acc[ni][1]);
                *(float2*)&pw[(g + 8) * 16 + ni * 8 + 2 * tq] = make_float2(acc[ni][2], acc[ni][3]);
            }
        }
        __syncthreads();

        {
            float gv[4];
#pragma unroll
            for (int gate = 0; gate < 4; gate++) {
                int ncol = gate * 8 + j_e;
                int w0 = (row_e >> 4) | ((ncol >> 4) << 1);
                int idx = (row_e & 15) * 16 + (ncol & 15);
                gv[gate] = part[w0 * 256 + idx] + part[(w0 + 4) * 256 + idx] + gpv[gate];
            }
            float iv = sigmoidf_(gv[0]);
            float jv = tanhf(gv[1]);
            float fv = sigmoidf_(gv[2]);
            float ov = sigmoidf_(gv[3]);
            float nc = fv * creg + iv * jv;
            float nh = ov * nc;                       // THUMT LSTMCell: activation=None
            creg = nc;
            __stwt(&out[(size_t)t * B_ * H_ + idx_h], nh);
            hout[idx_h] = __float2half(nh);
            if (has_tail && t == T_ - 1) { cf[idx_h] = nc; hf[idx_h] = nh; }
        }
#pragma unroll
        for (int gi = 0; gi < 4; gi++) gpv[gi] = gpn[gi];

        __syncthreads();
        if (tid == 0)
            asm volatile("red.release.gpu.global.add.s32 [%0], 1;"
                         :: "l"(ctr + t) : "memory");
    }
}

// ---------------- launch ------------------------------------------------------------
extern "C" void kernel_launch(void* const* d_in, const int* in_sizes, int n_in,
                              void* d_out, int out_size)
{
    (void)in_sizes; (void)n_in;
    const float* x  = (const float*)d_in[0];
    const float* sb = (const float*)d_in[1];
    const float* mem = (const float*)d_in[3];
    const float* Wq = (const float*)d_in[4];  const float* bq = (const float*)d_in[5];
    const float* Wk = (const float*)d_in[6];  const float* bk = (const float*)d_in[7];
    const float* Wv = (const float*)d_in[8];  const float* bv = (const float*)d_in[9];
    const float* Wo = (const float*)d_in[10]; const float* bo = (const float*)d_in[11];
    const float* W1 = (const float*)d_in[12]; const float* b1 = (const float*)d_in[13];
    const float* W2 = (const float*)d_in[14]; const float* b2 = (const float*)d_in[15];
    const float* Wg = (const float*)d_in[16]; const float* bg = (const float*)d_in[17];
    float* out = (float*)d_out;

    float *q, *k, *v, *ctxf, *attnf, *ffnhf, *ffnxf, *gpre, *hbuf, *cbuf, *wT, *xrf, *memrf;
    int* ctr;
    cudaGetSymbolAddress((void**)&q,    g_q);
    cudaGetSymbolAddress((void**)&k,    g_k);
    cudaGetSymbolAddress((void**)&v,    g_v);
    cudaGetSymbolAddress((void**)&ctxf, g_ctx);
    cudaGetSymbolAddress((void**)&attnf, g_attn);
    cudaGetSymbolAddress((void**)&ffnhf, g_ffnh);
    cudaGetSymbolAddress((void**)&ffnxf, g_ffnx);
    cudaGetSymbolAddress((void**)&gpre, g_gpre);
    cudaGetSymbolAddress((void**)&hbuf, g_hbuf);
    cudaGetSymbolAddress((void**)&cbuf, g_cbuf);
    cudaGetSymbolAddress((void**)&wT,   g_wT);
    cudaGetSymbolAddress((void**)&xrf,  g_xr);
    cudaGetSymbolAddress((void**)&memrf, g_memr);
    cudaGetSymbolAddress((void**)&ctr,  g_ctr);

    __half* ctx  = (__half*)ctxf;
    __half* attn = (__half*)attnf;
    __half* ffnh = (__half*)ffnhf;
    __half* ffnx = (__half*)ffnxf;
    __half* xh   = (__half*)xrf;
    __half* memh = (__half*)memrf;

    __half* WH  = (__half*)wT;
    __half* WqH = WH;
    __half* WkH = WH + (size_t)1 * MM_;
    __half* WvH = WH + (size_t)2 * MM_;
    __half* WoH = WH + (size_t)3 * MM_;
    __half* W1H = WH + (size_t)4 * MM_;
    __half* W2H = WH + (size_t)8 * MM_;
    __half* WgH = WH + (size_t)12 * MM_;
    __half* WhhH = WH + (size_t)20 * MM_;

    dim3 blk(256);

    // prepass: weights -> fp16 [N][K]; activations -> fp16
    transpose_f16<<<dim3(H_ / 32, H_ / 32), blk>>>(Wq, WqH, H_, H_);
    transpose_f16<<<dim3(H_ / 32, H_ / 32), blk>>>(Wk, WkH, H_, H_);
    transpose_f16<<<dim3(H_ / 32, H_ / 32), blk>>>(Wv, WvH, H_, H_);
    transpose_f16<<<dim3(H_ / 32, H_ / 32), blk>>>(Wo, WoH, H_, H_);
    transpose_f16<<<dim3(F_ / 32, H_ / 32), blk>>>(W1, W1H, H_, F_);
    transpose_f16<<<dim3(H_ / 32, F_ / 32), blk>>>(W2, W2H, F_, H_);
    transpose_f16<<<dim3(F_ / 32, (2 * H_) / 32), blk>>>(Wg, WgH, 2 * H_, F_);
    transpose_f16<<<dim3(F_ / 32, H_ / 32), blk>>>(
        Wg + (size_t)2 * H_ * 4 * H_, WhhH, H_, F_);
    round_f16<<<1024, blk>>>(x, xh, T_ * B_ * H_);
    round_f16<<<1024, blk>>>(mem, memh, S_ * B_ * H_);

    const int GSM = 4 * STG_;   // 81920
    cudaFuncSetAttribute(mm_gemm, cudaFuncAttributeMaxDynamicSharedMemorySize, GSM);
    cudaFuncSetAttribute(lstm_persist, cudaFuncAttributeMaxDynamicSharedMemorySize, LR_SMEM);

    // projections (fp16 in, fp32 out for attention)
    mm_gemm<<<dim3(H_ / 128, (T_ * B_) / 128), blk, GSM>>>(
        xh, xh, H_, WqH, bq, q, T_ * B_, H_, H_, 1);
    mm_gemm<<<dim3(H_ / 128, (S_ * B_) / 128), blk, GSM>>>(
        memh, memh, H_, WkH, bk, k, S_ * B_, H_, H_, 1);
    mm_gemm<<<dim3(H_ / 128, (S_ * B_) / 128), blk, GSM>>>(
        memh, memh, H_, WvH, bv, v, S_ * B_, H_, H_, 1);

    // attention (fp32 math, fp16 ctx out)
    size_t attn_smem = (size_t)ATT_SMEM_FLOATS * sizeof(float);
    cudaFuncSetAttribute(attn_kernel, cudaFuncAttributeMaxDynamicSharedMemorySize,
                         (int)attn_smem);
    attn_kernel<<<dim3(B_ * NH_, T_ / 64), blk, attn_smem>>>(q, k, v, sb, ctx);

    // output projection (fp16 out feeds gpre GEMM)
    mm_gemm<<<dim3(H_ / 128, (T_ * B_) / 128), blk, GSM>>>(
        ctx, ctx, H_, WoH, bo, attn, T_ * B_, H_, H_, 1 | 16);

    // feed-forward (fp16 chain)
    mm_gemm<<<dim3(F_ / 128, (T_ * B_) / 128), blk, GSM>>>(
        xh, xh, H_, W1H, b1, ffnh, T_ * B_, F_, H_, 1 | 2 | 16);
    mm_gemm<<<dim3(H_ / 128, (T_ * B_) / 128), blk, GSM>>>(
        ffnh, ffnh, F_, W2H, b2, ffnx, T_ * B_, H_, F_, 1 | 16);

    // gate precompute (fused dual-source K=2048): gpre = [ffnx|attn] @ WgH^T + bg
    mm_gemm<<<dim3((4 * H_) / 128, (T_ * B_) / 128), blk, GSM>>>(
        ffnx, attn, H_, WgH, bg, gpre, T_ * B_, 4 * H_, 2 * H_, 1);

    // recurrence: one persistent launch (fp16 h / Whh)
    init_state<<<(2 * B_ * H_ + 255) / 256, 256>>>(hbuf, cbuf, ctr);
    int has_tail = out_size >= T_ * B_ * H_ + 2 * B_ * H_;
    float* cf = out + (size_t)T_ * B_ * H_;
    float* hf = cf + B_ * H_;
    lstm_persist<<<128, blk, LR_SMEM>>>(gpre, WhhH, (__half*)hbuf, out, cf, hf,
                                        ctr, has_tail);
}

// round 16
// speedup vs baseline: 1.6451x; 1.0188x over previous
#include <cuda_runtime.h>
#include <cuda_fp16.h>
#include <math.h>
#include <stdint.h>

#define T_ 256
#define S_ 128
#define B_ 32
#define H_ 1024
#define NH_ 16
#define D_ 64
#define F_ 4096

// ---------------- scratch (static device globals; no allocation) ----------------
__device__ float g_q[(size_t)T_ * B_ * H_];
__device__ float g_k[(size_t)S_ * B_ * H_];
__device__ float g_v[(size_t)S_ * B_ * H_];
__device__ float g_ctx[(size_t)T_ * B_ * H_];    // used as __half
__device__ float g_attn[(size_t)T_ * B_ * H_];   // used as __half
__device__ float g_ffnh[(size_t)T_ * B_ * F_];   // used as __half
__device__ float g_ffnx[(size_t)T_ * B_ * H_];   // used as __half
__device__ float g_gpre[(size_t)T_ * B_ * 4 * H_];
__device__ float g_hbuf[2 * B_ * H_];            // used as __half[2][B*H]
__device__ float g_cbuf[B_ * H_];
__device__ float g_xr[(size_t)T_ * B_ * H_];     // used as __half (xh)
__device__ float g_memr[(size_t)S_ * B_ * H_];   // used as __half (memh)
__device__ int   g_ctr[T_];
// fp16 weights packed into g_wT (as __half): Wq 0, Wk 1M, Wv 2M, Wo 3M, W1 4M,
// W2 8M, Wg 12M, Whh 20M  (halves)
#define MM_ (1024 * 1024)
__device__ float g_wT[(size_t)24 * MM_];

// ---------------- PTX helpers ----------------------------------------------------
__device__ __forceinline__ uint32_t smem_to_u32(const void* p) {
    uint32_t a;
    asm("{ .reg .u64 t; cvta.to.shared.u64 t, %1; cvt.u32.u64 %0, t; }" : "=r"(a) : "l"(p));
    return a;
}
__device__ __forceinline__ void cp16(uint32_t s, const void* g) {
    asm volatile("cp.async.cg.shared.global [%0], [%1], 16;\n" :: "r"(s), "l"(g));
}
__device__ __forceinline__ void cp_commit() { asm volatile("cp.async.commit_group;\n"); }
template<int N> __device__ __forceinline__ void cp_wait() {
    asm volatile("cp.async.wait_group %0;\n" :: "n"(N));
}
__device__ __forceinline__ void ldsm4(uint32_t& r0, uint32_t& r1, uint32_t& r2,
                                      uint32_t& r3, uint32_t addr) {
    asm volatile("ldmatrix.sync.aligned.m8n8.x4.shared.b16 {%0,%1,%2,%3}, [%4];"
                 : "=r"(r0), "=r"(r1), "=r"(r2), "=r"(r3) : "r"(addr));
}
__device__ __forceinline__ void mma_f16(float (&d)[4], const uint32_t (&a)[4],
                                        uint32_t b0, uint32_t b1) {
    asm volatile(
        "mma.sync.aligned.m16n8k16.row.col.f32.f16.f16.f32 "
        "{%0,%1,%2,%3}, {%4,%5,%6,%7}, {%8,%9}, {%0,%1,%2,%3};\n"
        : "+f"(d[0]), "+f"(d[1]), "+f"(d[2]), "+f"(d[3])
        : "r"(a[0]), "r"(a[1]), "r"(a[2]), "r"(a[3]), "r"(b0), "r"(b1));
}
__device__ __forceinline__ float sigmoidf_(float x) { return 1.f / (1.f + __expf(-x)); }

// ---------------- prepass kernels -------------------------------------------------
__global__ __launch_bounds__(256)
void transpose_f16(const float* __restrict__ in, __half* __restrict__ out, int R, int C)
{
    __shared__ float t[32][33];
    const int bx = blockIdx.x * 32;
    const int by = blockIdx.y * 32;
    const int tx = threadIdx.x & 31;
    const int ty = threadIdx.x >> 5;
#pragma unroll
    for (int i = 0; i < 4; i++)
        t[ty + 8 * i][tx] = in[(size_t)(by + ty + 8 * i) * C + bx + tx];
    __syncthreads();
#pragma unroll
    for (int i = 0; i < 4; i++)
        out[(size_t)(bx + ty + 8 * i) * R + by + tx] = __float2half(t[tx][ty + 8 * i]);
}

__global__ __launch_bounds__(256)
void round_f16(const float* __restrict__ in, __half* __restrict__ out, int n)
{
    int i = blockIdx.x * 256 + threadIdx.x;
    for (; i < n; i += gridDim.x * 256)
        out[i] = __float2half(in[i]);
}

__global__ void init_state(float* h, float* cc, int* ctr)
{
    int i = blockIdx.x * 256 + threadIdx.x;
    if (i < 2 * B_ * H_) h[i] = 0.f;
    if (i < B_ * H_) cc[i] = 0.f;
    if (i < T_) ctr[i] = 0;
}

// ---------------- fp16 mma GEMM: C[MxN] = A @ Bt^T ---------------------------------
// A: [M][K] fp16, dual-source rows [A(kSplit) | A2(K-kSplit)]; Bt: [N][K] fp16.
// flags: 1=bias(fp32), 2=relu, 16=fp16 output (else fp32).
// 128x128 tile, K-tile=32 halves, 4-stage cp.async, m16n8k16 fragments.
#define STG_ 20480   // A 128*80 + B 128*80 (rows of 32 halves=64B + 16B pad)
__global__ __launch_bounds__(256, 2)
void mm_gemm(const __half* __restrict__ A, const __half* __restrict__ A2, int kSplit,
             const __half* __restrict__ Bt, const float* __restrict__ bias,
             void* __restrict__ Cout, int M, int N, int K, int flags)
{
    extern __shared__ char smc[];
    const uint32_t sb = smem_to_u32(smc);
    const int tid = threadIdx.x, lane = tid & 31, warp = tid >> 5;
    const int wm = warp >> 2, wn = warp & 3;
    const int m0 = blockIdx.y * 128, n0 = blockIdx.x * 128;
    const int lda2 = K - kSplit;
    const int nkt = K >> 5;

    auto fill = [&](int kt) {
        const int s = kt & 3;
        const uint32_t as = sb + s * STG_;
        const uint32_t bs = as + 10240;
        const int k0 = kt << 5;
#pragma unroll
        for (int i = 0; i < 2; i++) {
            int ch = tid + 256 * i;
            int row = ch >> 2, kh = ch & 3;
            int k = k0 + kh * 8;
            const __half* src = (k < kSplit)
                ? A  + (size_t)(m0 + row) * kSplit + k
                : A2 + (size_t)(m0 + row) * lda2 + (k - kSplit);
            cp16(as + row * 80 + kh * 16, src);
        }
#pragma unroll
        for (int i = 0; i < 2; i++) {
            int ch = tid + 256 * i;
            int row = ch >> 2, kh = ch & 3;
            cp16(bs + row * 80 + kh * 16, Bt + (size_t)(n0 + row) * K + k0 + kh * 8);
        }
    };

    float acc[4][4][4];
#pragma unroll
    for (int i = 0; i < 4; i++)
#pragma unroll
        for (int j = 0; j < 4; j++)
#pragma unroll
            for (int r = 0; r < 4; r++) acc[i][j][r] = 0.f;

    fill(0); cp_commit();
    fill(1); cp_commit();
    fill(2); cp_commit();

    const uint32_t aoff = (uint32_t)((wm * 64 + (lane & 15)) * 80 + (lane >> 4) * 16);
    const uint32_t boff = (uint32_t)((wn * 32 + (lane & 15)) * 80 + (lane >> 4) * 16);

    for (int kt = 0; kt < nkt; kt++) {
        cp_wait<2>();
        __syncthreads();
        if (kt + 3 < nkt) fill(kt + 3);
        cp_commit();
        const uint32_t as = sb + (kt & 3) * STG_;
        const uint32_t bs = as + 10240;
#pragma unroll
        for (int ks = 0; ks < 2; ks++) {       // two k16 halves of the 32-half tile
            uint32_t af[4][4], bf[2][4];
#pragma unroll
            for (int mi = 0; mi < 4; mi++)
                ldsm4(af[mi][0], af[mi][1], af[mi][2], af[mi][3],
                      as + aoff + mi * (16 * 80) + ks * 32);
#pragma unroll
            for (int nip = 0; nip < 2; nip++)
                ldsm4(bf[nip][0], bf[nip][1], bf[nip][2], bf[nip][3],
                      bs + boff + nip * (16 * 80) + ks * 32);
#pragma unroll
            for (int mi = 0; mi < 4; mi++)
#pragma unroll
                for (int ni = 0; ni < 4; ni++) {
                    const int nip = ni >> 1, o = ni & 1;
                    mma_f16(acc[mi][ni], af[mi], bf[nip][o], bf[nip][o + 2]);
                }
        }
    }

    const int g = lane >> 2, t = lane & 3;
#pragma unroll
    for (int mi = 0; mi < 4; mi++) {
#pragma unroll
        for (int ni = 0; ni < 4; ni++) {
            const int r0 = m0 + wm * 64 + mi * 16 + g;
            const int cc = n0 + wn * 32 + ni * 8 + 2 * t;
            float2 v0 = make_float2(acc[mi][ni][0], acc[mi][ni][1]);
            float2 v1 = make_float2(acc[mi][ni][2], acc[mi][ni][3]);
            if (flags & 1) {
                float2 bb = *(const float2*)(bias + cc);
                v0.x += bb.x; v0.y += bb.y; v1.x += bb.x; v1.y += bb.y;
            }
            if (flags & 2) {
                v0.x = fmaxf(v0.x, 0.f); v0.y = fmaxf(v0.y, 0.f);
                v1.x = fmaxf(v1.x, 0.f); v1.y = fmaxf(v1.y, 0.f);
            }
            if (flags & 16) {
                __half* C = (__half*)Cout;
                *(__half2*)(C + (size_t)r0 * N + cc) = __floats2half2_rn(v0.x, v0.y);
                *(__half2*)(C + (size_t)(r0 + 8) * N + cc) = __floats2half2_rn(v1.x, v1.y);
            } else {
                float* C = (float*)Cout;
                *(float2*)(C + (size_t)r0 * N + cc) = v0;
                *(float2*)(C + (size_t)(r0 + 8) * N + cc) = v1;
            }
        }
    }
}

// ---------------- attention (fp32 in, fp16 ctx out) ---------------------------------
#define ATT_PAD 68
#define ATT_SMEM_FLOATS ((64 + 128 + 128) * ATT_PAD + 8 * 128)

__global__ __launch_bounds__(256)
void attn_kernel(const float* __restrict__ q, const float* __restrict__ k,
                 const float* __restrict__ v, const float* __restrict__ sbias,
                 __half* __restrict__ ctx)
{
    extern __shared__ float sm[];
    float* Qs = sm;
    float* Ks = sm + 64 * ATT_PAD;
    float* Vs = Ks + 128 * ATT_PAD;
    float* probs = Vs + 128 * ATT_PAD;

    const int b = blockIdx.x / NH_;
    const int h = blockIdx.x % NH_;
    const int t0 = blockIdx.y * 64;
    const int tid = threadIdx.x;
    const int lane = tid & 31;
    const int warp = tid >> 5;
    const int hd = h * D_;

    for (int e = tid; e < 128 * 16; e += 256) {
        int s = e >> 4;
        int d4 = (e & 15) << 2;
        size_t gofs = ((size_t)(s * B_ + b)) * H_ + hd + d4;
        *(float4*)&Ks[s * ATT_PAD + d4] = *(const float4*)&k[gofs];
        *(float4*)&Vs[s * ATT_PAD + d4] = *(const float4*)&v[gofs];
    }
    for (int e = tid; e < 64 * 16; e += 256) {
        int r = e >> 4;
        int d4 = (e & 15) << 2;
        *(float4*)&Qs[r * ATT_PAD + d4] =
            *(const float4*)&q[((size_t)((t0 + r) * B_ + b)) * H_ + hd + d4];
    }
    __syncthreads();

    const float scale = 0.125f;
    float* pw = probs + warp * 128;

    for (int r8 = 0; r8 < 8; r8++) {
        int row = warp * 8 + r8;
        const float4* qrow = (const float4*)&Qs[row * ATT_PAD];
        const float4* k0p = (const float4*)&Ks[(lane) * ATT_PAD];
        const float4* k1p = (const float4*)&Ks[(lane + 32) * ATT_PAD];
        const float4* k2p = (const float4*)&Ks[(lane + 64) * ATT_PAD];
        const float4* k3p = (const float4*)&Ks[(lane + 96) * ATT_PAD];
        float a0 = 0.f, a1 = 0.f, a2 = 0.f, a3 = 0.f;
#pragma unroll
        for (int d4 = 0; d4 < 16; d4++) {
            float4 qv = qrow[d4];
            float4 kv;
            kv = k0p[d4]; a0 += qv.x*kv.x + qv.y*kv.y + qv.z*kv.z + qv.w*kv.w;
            kv = k1p[d4]; a1 += qv.x*kv.x + qv.y*kv.y + qv.z*kv.z + qv.w*kv.w;
            kv = k2p[d4]; a2 += qv.x*kv.x + qv.y*kv.y + qv.z*kv.z + qv.w*kv.w;
            kv = k3p[d4]; a3 += qv.x*kv.x + qv.y*kv.y + qv.z*kv.z + qv.w*kv.w;
        }
        a0 = a0 * scale + sbias[b * S_ + lane];
        a1 = a1 * scale + sbias[b * S_ + lane + 32];
        a2 = a2 * scale + sbias[b * S_ + lane + 64];
        a3 = a3 * scale + sbias[b * S_ + lane + 96];

        float mx = fmaxf(fmaxf(a0, a1), fmaxf(a2, a3));
#pragma unroll
        for (int off = 16; off; off >>= 1)
            mx = fmaxf(mx, __shfl_xor_sync(0xffffffffu, mx, off));
        float e0 = __expf(a0 - mx), e1 = __expf(a1 - mx);
        float e2 = __expf(a2 - mx), e3 = __expf(a3 - mx);
        float ssum = e0 + e1 + e2 + e3;
#pragma unroll
        for (int off = 16; off; off >>= 1)
            ssum += __shfl_xor_sync(0xffffffffu, ssum, off);
        float inv = 1.f / ssum;

        pw[lane] = e0 * inv; pw[lane + 32] = e1 * inv;
        pw[lane + 64] = e2 * inv; pw[lane + 96] = e3 * inv;
        __syncwarp();

        float c0 = 0.f, c1 = 0.f;
#pragma unroll 4
        for (int s = 0; s < 128; s++) {
            float p = pw[s];
            c0 += p * Vs[s * ATT_PAD + lane];
            c1 += p * Vs[s * ATT_PAD + lane + 32];
        }
        __half* crow = &ctx[((size_t)((t0 + row) * B_ + b)) * H_ + hd];
        crow[lane] = __float2half(c0);
        crow[lane + 32] = __float2half(c1);
        __syncwarp();
    }
}

// ---------------- persistent LSTM recurrence (fp16 MMA, 4x256 tiles) ----------------
// 128 CTAs, 1/SM. CTA n owns hidden cols [n*8, n*8+8) => 32 g-cols (4 gates x 8).
// Whh fp16 slice resident in smem. Per step: h streamed as 4 tiles of 256 halves
// (4 sync rounds, was 8); both warp k-groups compute every tile (k-split inside
// tile); tight-spin barrier (no nanosleep).
#define LR_BPITCH 2064
#define LR_APITCH 528                       // 256 halves + 16B pad (33 x 16B, odd)
#define LR_ATILE  (32 * LR_APITCH)          // 16896
#define LR_AOFF   (32 * LR_BPITCH)          // 66048
#define LR_POFF   (LR_AOFF + 4 * LR_ATILE)  // 133632
#define LR_SMEM   (LR_POFF + 8 * 256 * 4)   // 141824

__global__ __launch_bounds__(256, 1)
void lstm_persist(const float* __restrict__ gpre, const __half* __restrict__ WhhH,
                  __half* __restrict__ hbufH, float* __restrict__ out,
                  float* __restrict__ cf, float* __restrict__ hf,
                  int* __restrict__ ctr, int has_tail)
{
    extern __shared__ char smc[];
    const uint32_t sb = smem_to_u32(smc);
    const uint32_t Bs = sb;
    const uint32_t As = sb + LR_AOFF;
    float* part = (float*)(smc + LR_POFF);
    const int tid = threadIdx.x, lane = tid & 31, warp = tid >> 5;
    const int c0 = blockIdx.x * 8;

#pragma unroll 4
    for (int i = 0; i < 16; i++) {
        int id = tid + 256 * i;
        int row = id >> 7, ch = id & 127;
        int gate = row >> 3, j = row & 7;
        cp16(Bs + row * LR_BPITCH + ch * 16,
             WhhH + (size_t)(gate * H_ + c0 + j) * H_ + ch * 8);
    }
    cp_commit(); cp_wait<0>(); __syncthreads();

    const int wm = warp & 1, wn = (warp >> 1) & 1, wk = warp >> 2;
    const uint32_t aoff = (uint32_t)((wm * 16 + (lane & 15)) * LR_APITCH + (lane >> 4) * 16);
    const uint32_t boff = (uint32_t)((wn * 16 + (lane & 15)) * LR_BPITCH + (lane >> 4) * 16);
    const int row_e = tid >> 3, j_e = tid & 7;
    const int idx_h = row_e * H_ + c0 + j_e;

    float creg = 0.f;
    float gpv[4];
#pragma unroll
    for (int gi = 0; gi < 4; gi++)
        gpv[gi] = __ldg(gpre + (size_t)row_e * (4 * H_) + gi * H_ + c0 + j_e);

    for (int t = 0; t < T_; t++) {
        const __half* hin = hbufH + (t & 1) * (B_ * H_);
        __half* hout = hbufH + (1 - (t & 1)) * (B_ * H_);

        // deferred barrier wait (acquire, tight spin)
        if (t > 0) {
            if (tid == 0) {
                int v;
                do {
                    asm volatile("ld.acquire.gpu.global.s32 %0, [%1];"
                                 : "=r"(v) : "l"(ctr + t - 1) : "memory");
                } while (v < 128);
            }
            __syncthreads();
        }

        // stream whole h: 4 tiles of 256 halves, all fills up-front (4 groups)
#define LR_FILL(kt_) do { \
            const uint32_t as_f = As + (kt_) * LR_ATILE; \
            _Pragma("unroll") \
            for (int i_ = 0; i_ < 4; i_++) { \
                int id_ = tid + 256 * i_; \
                int row_ = id_ >> 5, ch_ = id_ & 31; \
                cp16(as_f + row_ * LR_APITCH + ch_ * 16, \
                     hin + row_ * H_ + (kt_) * 256 + ch_ * 8); \
            } \
            cp_commit(); \
        } while (0)
        LR_FILL(0); LR_FILL(1); LR_FILL(2); LR_FILL(3);

        float acc[2][4];
#pragma unroll
        for (int i = 0; i < 2; i++)
#pragma unroll
            for (int r = 0; r < 4; r++) acc[i][r] = 0.f;

#define LR_STEP(kt_, w_) do { \
            cp_wait<w_>(); \
            __syncthreads(); \
            const uint32_t as_ = As + (kt_) * LR_ATILE + aoff; \
            const uint32_t bk_ = Bs + boff + (kt_) * 512; \
            _Pragma("unroll") \
            for (int s8 = 0; s8 < 8; s8++) { \
                const int s = wk * 8 + s8; \
                uint32_t af[4], b0, b1, b2, b3; \
                ldsm4(af[0], af[1], af[2], af[3], as_ + s * 32); \
                ldsm4(b0, b1, b2, b3, bk_ + s * 32); \
                mma_f16(acc[0], af, b0, b2); \
                mma_f16(acc[1], af, b1, b3); \
            } \
        } while (0)
        LR_STEP(0, 3); LR_STEP(1, 2); LR_STEP(2, 1); LR_STEP(3, 0);

        // prefetch next step's gate bias early (overlaps epilogue + barrier)
        float gpn[4] = {0.f, 0.f, 0.f, 0.f};
        if (t + 1 < T_) {
            const float* gp1 = gpre + (size_t)(t + 1) * B_ * 4 * H_;
#pragma unroll
            for (int gi = 0; gi < 4; gi++)
                gpn[gi] = __ldg(gp1 + (size_t)row_e * (4 * H_) + gi * H_ + c0 + j_e);
        }

        // store per-warp partials [16x16]
        {
            const int g = lane >> 2, tq = lane & 3;
            float* pw = part + warp * 256;
#pragma unroll
            for (int ni = 0; ni < 2; ni++) {
                *(float2*)&pw[g * 16 + ni * 8 + 2 * tq] = make_float2(acc[ni][0], acc[ni][1]);
                *(float2*)&pw[(g + 8) * 16 + ni * 8 + 2 * tq] = make_float2(acc[ni][2], acc[ni][3]);
            }
        }
        __syncthreads();

        // combine k-halves + gpre; gates; state update (c carried in register)
        {
            float gv[4];
#pragma unroll
            for (int gate = 0; gate < 4; gate++) {
                int ncol = gate * 8 + j_e;
                int w0 = (row_e >> 4) | ((ncol >> 4) << 1);
                int idx = (row_e & 15) * 16 + (ncol & 15);
                gv[gate] = part[w0 * 256 + idx] + part[(w0 + 4) * 256 + idx] + gpv[gate];
            }
            float iv = sigmoidf_(gv[0]);
            float jv = tanhf(gv[1]);
            float fv = sigmoidf_(gv[2]);
            float ov = sigmoidf_(gv[3]);
            float nc = fv * creg + iv * jv;
            float nh = ov * nc;                       // THUMT LSTMCell: activation=None
            creg = nc;
            __stwt(&out[(size_t)t * B_ * H_ + idx_h], nh);
            hout[idx_h] = __float2half(nh);
            if (has_tail && t == T_ - 1) { cf[idx_h] = nc; hf[idx_h] = nh; }
        }
#pragma unroll
        for (int gi = 0; gi < 4; gi++) gpv[gi] = gpn[gi];

        // barrier arrival (release; no gpu fence -> no L1D flush)
        __syncthreads();
        if (tid == 0)
            asm volatile("red.release.gpu.global.add.s32 [%0], 1;"
                         :: "l"(ctr + t) : "memory");
    }
}

// ---------------- launch ------------------------------------------------------------
extern "C" void kernel_launch(void* const* d_in, const int* in_sizes, int n_in,
                              void* d_out, int out_size)
{
    (void)in_sizes; (void)n_in;
    const float* x  = (const float*)d_in[0];
    const float* sb = (const float*)d_in[1];
    const float* mem = (const float*)d_in[3];
    const float* Wq = (const float*)d_in[4];  const float* bq = (const float*)d_in[5];
    const float* Wk = (const float*)d_in[6];  const float* bk = (const float*)d_in[7];
    const float* Wv = (const float*)d_in[8];  const float* bv = (const float*)d_in[9];
    const float* Wo = (const float*)d_in[10]; const float* bo = (const float*)d_in[11];
    const float* W1 = (const float*)d_in[12]; const float* b1 = (const float*)d_in[13];
    const float* W2 = (const float*)d_in[14]; const float* b2 = (const float*)d_in[15];
    const float* Wg = (const float*)d_in[16]; const float* bg = (const float*)d_in[17];
    float* out = (float*)d_out;

    float *q, *k, *v, *ctxf, *attnf, *ffnhf, *ffnxf, *gpre, *hbuf, *cbuf, *wT, *xrf, *memrf;
    int* ctr;
    cudaGetSymbolAddress((void**)&q,    g_q);
    cudaGetSymbolAddress((void**)&k,    g_k);
    cudaGetSymbolAddress((void**)&v,    g_v);
    cudaGetSymbolAddress((void**)&ctxf, g_ctx);
    cudaGetSymbolAddress((void**)&attnf, g_attn);
    cudaGetSymbolAddress((void**)&ffnhf, g_ffnh);
    cudaGetSymbolAddress((void**)&ffnxf, g_ffnx);
    cudaGetSymbolAddress((void**)&gpre, g_gpre);
    cudaGetSymbolAddress((void**)&hbuf, g_hbuf);
    cudaGetSymbolAddress((void**)&cbuf, g_cbuf);
    cudaGetSymbolAddress((void**)&wT,   g_wT);
    cudaGetSymbolAddress((void**)&xrf,  g_xr);
    cudaGetSymbolAddress((void**)&memrf, g_memr);
    cudaGetSymbolAddress((void**)&ctr,  g_ctr);

    __half* ctx  = (__half*)ctxf;
    __half* attn = (__half*)attnf;
    __half* ffnh = (__half*)ffnhf;
    __half* ffnx = (__half*)ffnxf;
    __half* xh   = (__half*)xrf;
    __half* memh = (__half*)memrf;

    __half* WH  = (__half*)wT;
    __half* WqH = WH;
    __half* WkH = WH + (size_t)1 * MM_;
    __half* WvH = WH + (size_t)2 * MM_;
    __half* WoH = WH + (size_t)3 * MM_;
    __half* W1H = WH + (size_t)4 * MM_;
    __half* W2H = WH + (size_t)8 * MM_;
    __half* WgH = WH + (size_t)12 * MM_;
    __half* WhhH = WH + (size_t)20 * MM_;

    dim3 blk(256);

    // prepass: weights -> fp16 [N][K]; activations -> fp16
    transpose_f16<<<dim3(H_ / 32, H_ / 32), blk>>>(Wq, WqH, H_, H_);
    transpose_f16<<<dim3(H_ / 32, H_ / 32), blk>>>(Wk, WkH, H_, H_);
    transpose_f16<<<dim3(H_ / 32, H_ / 32), blk>>>(Wv, WvH, H_, H_);
    transpose_f16<<<dim3(H_ / 32, H_ / 32), blk>>>(Wo, WoH, H_, H_);
    transpose_f16<<<dim3(F_ / 32, H_ / 32), blk>>>(W1, W1H, H_, F_);
    transpose_f16<<<dim3(H_ / 32, F_ / 32), blk>>>(W2, W2H, F_, H_);
    transpose_f16<<<dim3(F_ / 32, (2 * H_) / 32), blk>>>(Wg, WgH, 2 * H_, F_);
    transpose_f16<<<dim3(F_ / 32, H_ / 32), blk>>>(
        Wg + (size_t)2 * H_ * 4 * H_, WhhH, H_, F_);
    round_f16<<<1024, blk>>>(x, xh, T_ * B_ * H_);
    round_f16<<<1024, blk>>>(mem, memh, S_ * B_ * H_);

    const int GSM = 4 * STG_;   // 81920
    cudaFuncSetAttribute(mm_gemm, cudaFuncAttributeMaxDynamicSharedMemorySize, GSM);
    cudaFuncSetAttribute(lstm_persist, cudaFuncAttributeMaxDynamicSharedMemorySize, LR_SMEM);

    // projections (fp16 in, fp32 out for attention)
    mm_gemm<<<dim3(H_ / 128, (T_ * B_) / 128), blk, GSM>>>(
        xh, xh, H_, WqH, bq, q, T_ * B_, H_, H_, 1);
    mm_gemm<<<dim3(H_ / 128, (S_ * B_) / 128), blk, GSM>>>(
        memh, memh, H_, WkH, bk, k, S_ * B_, H_, H_, 1);
    mm_gemm<<<dim3(H_ / 128, (S_ * B_) / 128), blk, GSM>>>(
        memh, memh, H_, WvH, bv, v, S_ * B_, H_, H_, 1);

    // attention (fp32 math, fp16 ctx out)
    size_t attn_smem = (size_t)ATT_SMEM_FLOATS * sizeof(float);
    cudaFuncSetAttribute(attn_kernel, cudaFuncAttributeMaxDynamicSharedMemorySize,
                         (int)attn_smem);
    attn_kernel<<<dim3(B_ * NH_, T_ / 64), blk, attn_smem>>>(q, k, v, sb, ctx);

    // output projection (fp16 out feeds gpre GEMM)
    mm_gemm<<<dim3(H_ / 128, (T_ * B_) / 128), blk, GSM>>>(
        ctx, ctx, H_, WoH, bo, attn, T_ * B_, H_, H_, 1 | 16);

    // feed-forward (fp16 chain)
    mm_gemm<<<dim3(F_ / 128, (T_ * B_) / 128), blk, GSM>>>(
        xh, xh, H_, W1H, b1, ffnh, T_ * B_, F_, H_, 1 | 2 | 16);
    mm_gemm<<<dim3(H_ / 128, (T_ * B_) / 128), blk, GSM>>>(
        ffnh, ffnh, F_, W2H, b2, ffnx, T_ * B_, H_, F_, 1 | 16);

    // gate precompute (fused dual-source K=2048): gpre = [ffnx|attn] @ WgH^T + bg
    mm_gemm<<<dim3((4 * H_) / 128, (T_ * B_) / 128), blk, GSM>>>(
        ffnx, attn, H_, WgH, bg, gpre, T_ * B_, 4 * H_, 2 * H_, 1);

    // recurrence: one persistent launch (fp16 h / Whh)
    init_state<<<(2 * B_ * H_ + 255) / 256, 256>>>(hbuf, cbuf, ctr);
    int has_tail = out_size >= T_ * B_ * H_ + 2 * B_ * H_;
    float* cf = out + (size_t)T_ * B_ * H_;
    float* hf = cf + B_ * H_;
    lstm_persist<<<128, blk, LR_SMEM>>>(gpre, WhhH, (__half*)hbuf, out, cf, hf,
                                        ctr, has_tail);
}